// round 13
// baseline (speedup 1.0000x reference)
#include <cuda_runtime.h>
#include <cuda_bf16.h>
#include <math.h>
#include <stdint.h>

// ---------------- problem constants ----------------
#define BSZ     2048
#define NE      64
#define NA      16
#define DIN     128
#define HD      512
#define AD      256
#define NHD     8
#define ED      32
#define RLD     64
#define OUTD    128
#define M_FULL  (BSZ*NE)     // 131072
#define M_AG    (BSZ*NA)     // 32768
#define GID     1536         // 3*H

// ---------------- scratch (device globals; no allocs allowed) ----------------
__device__ __align__(256) float g_KV [(size_t)M_FULL*2*AD];   // K|V packed per row
__device__ __align__(256) float g_Q  [(size_t)M_AG*AD];
__device__ __align__(256) float g_gi [(size_t)M_AG*GID];
__device__ __align__(256) float g_gh [(size_t)M_AG*GID];
__device__ __align__(256) float g_state_t[(size_t)M_FULL*DIN];
__device__ __align__(256) float g_embed_t[(size_t)M_FULL*HD];
__device__ __align__(256) float g_preh_t [(size_t)M_AG*HD];
__device__ __align__(256) float g_att_t  [(size_t)M_AG*AD];
__device__ __align__(256) float g_rew_t  [(size_t)BSZ*RLD];
__device__ __align__(256) float g_h_t    [(size_t)M_AG*HD];
__device__ __align__(256) float g_WstT [HD*DIN];
__device__ __align__(256) float g_WqT  [AD*HD];
__device__ __align__(256) float g_WkvT [2*AD*HD];
__device__ __align__(256) float g_bkv  [2*AD];
__device__ __align__(256) float g_WihT [GID*832];
__device__ __align__(256) float g_WhhT [GID*HD];
__device__ __align__(256) float g_WoutT[OUTD*HD];
__device__ unsigned char g_obs_u8[(size_t)BSZ*NE*NE];
__device__ unsigned char g_sm_u8 [(size_t)BSZ*NE];
__device__ int g_mask_flags;

// ---------------- baseline-PTX helpers ----------------
__device__ __forceinline__ uint32_t smem_u32(const void* p) {
    uint32_t a;
    asm("{ .reg .u64 t; cvta.to.shared.u64 t, %1; cvt.u32.u64 %0, t; }" : "=r"(a) : "l"(p));
    return a;
}
__device__ __forceinline__ void cp16(uint32_t dst, const void* src) {
    asm volatile("cp.async.cg.shared.global [%0], [%1], 16;" :: "r"(dst), "l"(src));
}
#define CP_COMMIT()  asm volatile("cp.async.commit_group;")
#define CP_WAIT(n)   asm volatile("cp.async.wait_group %0;" :: "n"(n))

__device__ __forceinline__ void ldm_x4(uint32_t* r, uint32_t addr) {
    asm volatile("ldmatrix.sync.aligned.m8n8.x4.shared.b16 {%0,%1,%2,%3}, [%4];"
                 : "=r"(r[0]), "=r"(r[1]), "=r"(r[2]), "=r"(r[3]) : "r"(addr));
}
__device__ __forceinline__ void mma_tf32(float* c, const uint32_t* a,
                                         uint32_t b0, uint32_t b1) {
    asm volatile(
        "mma.sync.aligned.m16n8k8.row.col.f32.tf32.tf32.f32 "
        "{%0,%1,%2,%3},{%4,%5,%6,%7},{%8,%9},{%0,%1,%2,%3};"
        : "+f"(c[0]), "+f"(c[1]), "+f"(c[2]), "+f"(c[3])
        : "r"(a[0]), "r"(a[1]), "r"(a[2]), "r"(a[3]), "r"(b0), "r"(b1));
}
__device__ __forceinline__ float rna_tf32(float v) {
    uint32_t r;
    asm("cvt.rna.tf32.f32 %0, %1;" : "=r"(r) : "f"(v));
    return __uint_as_float(r);
}

// ---------------- fused prep ----------------
#define PREP_TOTAL 2589184
__global__ void prep_weights_kernel(
    const float* __restrict__ Wst, const float* __restrict__ Wq,
    const float* __restrict__ Wk,  const float* __restrict__ Wv,
    const float* __restrict__ Wih, const float* __restrict__ Whh,
    const float* __restrict__ Wout,
    const float* __restrict__ bk,  const float* __restrict__ bv)
{
    int i = blockIdx.x * blockDim.x + threadIdx.x;
    if (i == 0) g_mask_flags = 0;
    if (i >= PREP_TOTAL) return;

    const float* src; float* dst; int K, N, j;
    if (i < 65536)        { j = i;           src = Wst;  dst = g_WstT;  K = DIN; N = HD; }
    else if (i < 196608)  { j = i - 65536;   src = Wq;   dst = g_WqT;   K = HD;  N = AD; }
    else if (i < 327680)  { j = i - 196608;  src = Wk;   dst = g_WkvT;  K = HD;  N = AD; }
    else if (i < 458752)  { j = i - 327680;  src = Wv;   dst = g_WkvT + AD*HD; K = HD; N = AD; }
    else if (i < 1736704) { j = i - 458752;  src = Wih;  dst = g_WihT;  K = 832; N = GID; }
    else if (i < 2523136) { j = i - 1736704; src = Whh;  dst = g_WhhT;  K = HD;  N = GID; }
    else if (i < 2588672) { j = i - 2523136; src = Wout; dst = g_WoutT; K = HD;  N = OUTD; }
    else {
        j = i - 2588672;
        g_bkv[j] = (j < AD) ? bk[j] : bv[j - AD];
        return;
    }
    int k = j / N, n = j % N;
    dst[(size_t)n * K + k] = rna_tf32(src[j]);
}

#define ACT_N4A (M_FULL*DIN/4)
#define ACT_N4B (M_AG*HD/4)
__global__ void conv_acts_kernel(const float* __restrict__ state,
                                 const float* __restrict__ preh)
{
    int i = blockIdx.x * blockDim.x + threadIdx.x;
    const float4* src; float4* dst; int j;
    if (i < ACT_N4A)                { j = i;           src = (const float4*)state; dst = (float4*)g_state_t; }
    else if (i < ACT_N4A + ACT_N4B) { j = i - ACT_N4A; src = (const float4*)preh;  dst = (float4*)g_preh_t; }
    else return;
    float4 v = src[j];
    v.x = rna_tf32(v.x); v.y = rna_tf32(v.y);
    v.z = rna_tf32(v.z); v.w = rna_tf32(v.w);
    dst[j] = v;
}

// ---------------- mask dtype detection + conversion ----------------
__global__ void detect_mask_kernel(const unsigned int* __restrict__ w, int nwords)
{
    int local = 0;
    for (int i = blockIdx.x * blockDim.x + threadIdx.x; i < nwords;
         i += gridDim.x * blockDim.x) {
        unsigned int v = w[i];
        if (v == 0x3F800000u) local |= 2;
        else if (v > 1u) local |= 1;
    }
    for (int d = 16; d > 0; d >>= 1) local |= __shfl_xor_sync(0xffffffffu, local, d);
    if ((threadIdx.x & 31) == 0 && local) atomicOr(&g_mask_flags, local);
}

#define OBS4 (BSZ*NE*NE/4)
#define SM4  (BSZ*NE/4)
__device__ __forceinline__ void conv4(const void* __restrict__ src,
                                      unsigned char* __restrict__ dst,
                                      int i, int mode)
{
    uchar4 o;
    if (mode == 1) {
        uchar4 v = ((const uchar4*)src)[i];
        o = make_uchar4(v.x != 0, v.y != 0, v.z != 0, v.w != 0);
    } else {
        uint4 v = ((const uint4*)src)[i];
        o = make_uchar4(v.x != 0, v.y != 0, v.z != 0, v.w != 0);
    }
    ((uchar4*)dst)[i] = o;
}
__global__ void convert_masks_kernel(const void* __restrict__ obs_src,
                                     const void* __restrict__ sm_src)
{
    int i = blockIdx.x * blockDim.x + threadIdx.x;
    int f = g_mask_flags;
    int mode = (f & 2) ? 2 : ((f & 1) ? 1 : 0);
    if (i < OBS4)            conv4(obs_src, g_obs_u8, i, mode);
    else if (i < OBS4 + SM4) conv4(sm_src,  g_sm_u8,  i - OBS4, mode);
}

// ---------------- tf32 HMMA GEMM ----------------
// BN=256: 512 threads, warp grid 4x4, warp tile 32x64 (acc 64 regs).
// BN=128: 256 threads, warp grid 4x2, warp tile 32x64.
enum { MODE_DIR = 0, MODE_G16 = 1, MODE_CAT = 2 };
enum { EPI_F32 = 0, EPI_RELU = 1, EPI_MASK = 2, EPI_RELU_RND = 3, EPI_KV = 4 };

template<int BN> struct GP {
    static const int THREADS    = (BN == 256) ? 512 : 256;
    static const int STAGE_ROWS = 128 + BN;
    static const int STAGE_SZ   = STAGE_ROWS * 128;
    static const int SMEM       = 4 * STAGE_SZ;
};

template<int MODE>
__device__ __forceinline__ const float* a_src(const float* A, const float* A2, const float* A3,
                                              int m, int K, int k0)
{
    if (MODE == MODE_CAT) {
        if (k0 < 512) return A  + (size_t)((m >> 4) * 64 + (m & 15)) * 512 + k0;
        if (k0 < 768) return A2 + (size_t)m * 256 + (k0 - 512);
        return A3 + (size_t)(m >> 4) * 64 + (k0 - 768);
    } else if (MODE == MODE_G16) {
        return A + (size_t)((m >> 4) * 64 + (m & 15)) * K + k0;
    } else {
        return A + (size_t)m * K + k0;
    }
}

template<int BN, int MODE, int EPI>
__global__ void __launch_bounds__(GP<BN>::THREADS, 1)
gemm_tf32(const float* __restrict__ A, const float* __restrict__ A2,
          const float* __restrict__ A3, const float* __restrict__ B,  // [N,K]
          const float* __restrict__ bias, float* __restrict__ C,
          const unsigned char* __restrict__ smask,
          int K, int ldc)
{
    extern __shared__ char sm[];
    const uint32_t smb = smem_u32(sm);
    const int tid  = threadIdx.x;
    const int wid  = tid >> 5;
    const int lane = tid & 31;
    const int bm = blockIdx.y * 128;
    const int bn = blockIdx.x * BN;

    const int warp_m = wid & 3;          // 4 warps in M: 32 rows each
    const int warp_n = wid >> 2;         // 2 or 4 warps in N: 64 cols each

    float acc[2][8][4];
    #pragma unroll
    for (int mt = 0; mt < 2; mt++)
        #pragma unroll
        for (int nt = 0; nt < 8; nt++)
            #pragma unroll
            for (int r = 0; r < 4; r++) acc[mt][nt][r] = 0.0f;

    const int nch = K / 32;

    auto load_stage = [&](int s, int k0) {
        const uint32_t stg = smb + s * GP<BN>::STAGE_SZ;
        const int iters = GP<BN>::STAGE_ROWS * 8 / GP<BN>::THREADS;
        #pragma unroll
        for (int it = 0; it < iters; it++) {
            int idx  = tid + it * GP<BN>::THREADS;
            int grow = idx >> 3;
            int c16  = idx & 7;
            uint32_t dst = stg + grow * 128 + (uint32_t)((c16 ^ (grow & 7)) * 16);
            const float* src;
            if (grow < 128) src = a_src<MODE>(A, A2, A3, bm + grow, K, k0) + c16 * 4;
            else            src = B + (size_t)(bn + grow - 128) * K + k0 + c16 * 4;
            cp16(dst, src);
        }
    };

    load_stage(0, 0);
    CP_COMMIT();
    if (nch > 1) { load_stage(1, 32); CP_COMMIT(); }
    if (nch > 2) { load_stage(2, 64); CP_COMMIT(); }

    const int T = lane >> 3;
    const int tr = lane & 7;

    for (int c = 0; c < nch; c++) {
        const int rem = nch - 1 - c;
        if (rem >= 2)      { CP_WAIT(2); }
        else if (rem == 1) { CP_WAIT(1); }
        else               { CP_WAIT(0); }
        __syncthreads();

        const uint32_t stg = smb + (c & 3) * GP<BN>::STAGE_SZ;
        #pragma unroll
        for (int s = 0; s < 4; s++) {
            uint32_t a[2][4];
            #pragma unroll
            for (int mt = 0; mt < 2; mt++) {
                uint32_t row = warp_m * 32 + mt * 16 + (T & 1) * 8 + tr;
                uint32_t chk = 2 * s + (T >> 1);
                ldm_x4(a[mt], stg + row * 128 + ((chk ^ (row & 7)) * 16));
            }
            #pragma unroll
            for (int nq = 0; nq < 4; nq++) {
                uint32_t nrow = 128 + warp_n * 64 + nq * 16 + (T >> 1) * 8 + tr;
                uint32_t chk = 2 * s + (T & 1);
                uint32_t b[4];
                ldm_x4(b, stg + nrow * 128 + ((chk ^ (nrow & 7)) * 16));
                #pragma unroll
                for (int mt = 0; mt < 2; mt++) {
                    mma_tf32(acc[mt][nq * 2 + 0], a[mt], b[0], b[1]);
                    mma_tf32(acc[mt][nq * 2 + 1], a[mt], b[2], b[3]);
                }
            }
        }

        if (c + 3 < nch) {
            load_stage((c + 3) & 3, (c + 3) * 32);
            CP_COMMIT();
        }
    }

    #pragma unroll
    for (int mt = 0; mt < 2; mt++) {
        #pragma unroll
        for (int nt = 0; nt < 8; nt++) {
            const int row0 = bm + warp_m * 32 + mt * 16 + (lane >> 2);
            const int col  = bn + warp_n * 64 + nt * 8 + (lane & 3) * 2;
            const float b0 = bias[col], b1 = bias[col + 1];
            #pragma unroll
            for (int h = 0; h < 2; h++) {
                const int row = row0 + h * 8;
                float v0 = acc[mt][nt][h * 2 + 0] + b0;
                float v1 = acc[mt][nt][h * 2 + 1] + b1;
                if (EPI == EPI_RELU || EPI == EPI_RELU_RND) {
                    v0 = fmaxf(v0, 0.0f); v1 = fmaxf(v1, 0.0f);
                }
                if (EPI == EPI_KV && col >= AD) {
                    v0 = fmaxf(v0, 0.0f); v1 = fmaxf(v1, 0.0f);
                }
                if (EPI == EPI_MASK) {
                    const int b = row >> 4, q = row & 15;
                    const float keep = smask[b * 64 + q] ? 0.0f : 1.0f;
                    v0 *= keep; v1 *= keep;
                }
                if (EPI == EPI_RELU_RND) { v0 = rna_tf32(v0); v1 = rna_tf32(v1); }
                *(float2*)(C + (size_t)row * ldc + col) = make_float2(v0, v1);
            }
        }
    }
}

// ---------------- reward projection ----------------
__global__ void rew_kernel(const float* __restrict__ prer,
                           const float* __restrict__ Wr,
                           const float* __restrict__ br,
                           float* __restrict__ out)
{
    int idx = blockIdx.x * blockDim.x + threadIdx.x;
    if (idx >= BSZ * RLD) return;
    int b = idx >> 6, j = idx & 63;
    out[idx] = rna_tf32(fmaxf(fmaf(prer[b], Wr[j], br[j]), 0.0f));
}

// ---------------- attention ----------------
__global__ void __launch_bounds__(128)
attn_kernel(const float* __restrict__ Qg, const float* __restrict__ KVg,
            const unsigned char* __restrict__ obs, float* __restrict__ outT)
{
    const int b = blockIdx.x >> 3;
    const int h = blockIdx.x & 7;
    const int tid = threadIdx.x;

    __shared__ float Qs[16][32];
    __shared__ float Ks[64][33];
    __shared__ float Vs[64][32];
    __shared__ float Ws[16][68];

    {
        int q = tid >> 3;
        int e4 = (tid & 7) * 4;
        *(float4*)&Qs[q][e4] =
            *(const float4*)(Qg + (size_t)(b * 16 + q) * 256 + h * 32 + e4);
    }
    #pragma unroll
    for (int i = 0; i < 4; i++) {
        int idx = tid + i * 128;
        int k = idx >> 3;
        int e4 = (idx & 7) * 4;
        const float* kvrow = KVg + (size_t)(b * 64 + k) * 512 + h * 32 + e4;
        float4 kv = *(const float4*)kvrow;
        Ks[k][e4 + 0] = kv.x; Ks[k][e4 + 1] = kv.y;
        Ks[k][e4 + 2] = kv.z; Ks[k][e4 + 3] = kv.w;
        *(float4*)&Vs[k][e4] = *(const float4*)(kvrow + 256);
    }
    __syncthreads();

    const float scale = 0.17677669529663687f;
    #pragma unroll
    for (int i = 0; i < 8; i++) {
        int s = tid + i * 128;
        int q = s >> 6;
        int k = s & 63;
        bool masked = (k == q) || (obs[(size_t)b * 4096 + q * 64 + k] != 0);
        float d;
        if (!masked) {
            d = 0.0f;
            #pragma unroll
            for (int e = 0; e < 32; e++) d = fmaf(Qs[q][e], Ks[k][e], d);
            d *= scale;
        } else {
            d = -INFINITY;
        }
        Ws[q][k] = d;
    }
    __syncthreads();

    {
        int q = tid >> 3;
        int l = tid & 7;
        float vals[8];
        float mx = -INFINITY;
        #pragma unroll
        for (int i = 0; i < 8; i++) { vals[i] = Ws[q][l + i * 8]; mx = fmaxf(mx, vals[i]); }
        #pragma unroll
        for (int d2 = 4; d2 > 0; d2 >>= 1) mx = fmaxf(mx, __shfl_xor_sync(0xffffffffu, mx, d2, 8));
        if (mx == -INFINITY) {
            #pragma unroll
            for (int i = 0; i < 8; i++) vals[i] = 0.0f;
        } else {
            float sum = 0.0f;
            #pragma unroll
            for (int i = 0; i < 8; i++) { vals[i] = __expf(vals[i] - mx); sum += vals[i]; }
            #pragma unroll
            for (int d2 = 4; d2 > 0; d2 >>= 1) sum += __shfl_xor_sync(0xffffffffu, sum, d2, 8);
            float inv = 1.0f / sum;
            #pragma unroll
            for (int i = 0; i < 8; i++) vals[i] *= inv;
        }
        #pragma unroll
        for (int i = 0; i < 8; i++) Ws[q][l + i * 8] = vals[i];
    }
    __syncthreads();

    #pragma unroll
    for (int i = 0; i < 4; i++) {
        int o = tid + i * 128;
        int q = o >> 5;
        int e = o & 31;
        float acc = 0.0f;
        #pragma unroll
        for (int k = 0; k < 64; k++) acc = fmaf(Ws[q][k], Vs[k][e], acc);
        outT[(size_t)(b * 16 + q) * 256 + h * 32 + e] = rna_tf32(acc);
    }
}

// ---------------- GRU pointwise ----------------
__device__ __forceinline__ float sigmoidf_(float x) { return 1.0f / (1.0f + __expf(-x)); }

__global__ void gru_kernel(const float* __restrict__ gi, const float* __restrict__ gh,
                           const float* __restrict__ preh,
                           const unsigned char* __restrict__ smask,
                           float* __restrict__ hOut, float* __restrict__ hT)
{
    int t = blockIdx.x * blockDim.x + threadIdx.x;
    if (t >= M_AG * (HD / 4)) return;
    int m  = t >> 7;
    int j4 = (t & 127) * 4;
    size_t gb = (size_t)m * GID + j4;
    size_t hb = (size_t)m * HD + j4;

    float4 ir = *(const float4*)(gi + gb);
    float4 iz = *(const float4*)(gi + gb + 512);
    float4 in = *(const float4*)(gi + gb + 1024);
    float4 hr = *(const float4*)(gh + gb);
    float4 hz = *(const float4*)(gh + gb + 512);
    float4 hn = *(const float4*)(gh + gb + 1024);
    float4 hp = *(const float4*)(preh + hb);

    int b = m >> 4, q = m & 15;
    float keep = smask[b * 64 + q] ? 0.0f : 1.0f;

    float o[4];
    {
        float r = sigmoidf_(ir.x + hr.x), z = sigmoidf_(iz.x + hz.x);
        float n = tanhf(in.x + r * hn.x);
        o[0] = keep * ((1.0f - z) * n + z * hp.x);
    }
    {
        float r = sigmoidf_(ir.y + hr.y), z = sigmoidf_(iz.y + hz.y);
        float n = tanhf(in.y + r * hn.y);
        o[1] = keep * ((1.0f - z) * n + z * hp.y);
    }
    {
        float r = sigmoidf_(ir.z + hr.z), z = sigmoidf_(iz.z + hz.z);
        float n = tanhf(in.z + r * hn.z);
        o[2] = keep * ((1.0f - z) * n + z * hp.z);
    }
    {
        float r = sigmoidf_(ir.w + hr.w), z = sigmoidf_(iz.w + hz.w);
        float n = tanhf(in.w + r * hn.w);
        o[3] = keep * ((1.0f - z) * n + z * hp.w);
    }
    *(float4*)(hOut + hb) = make_float4(o[0], o[1], o[2], o[3]);
    *(float4*)(hT + hb) = make_float4(rna_tf32(o[0]), rna_tf32(o[1]),
                                      rna_tf32(o[2]), rna_tf32(o[3]));
}

// ---------------- launch ----------------
extern "C" void kernel_launch(void* const* d_in, const int* in_sizes, int n_in,
                              void* d_out, int out_size)
{
    (void)in_sizes; (void)out_size;

    const float* state          = (const float*)d_in[0];
    const float* prer           = (const float*)d_in[1];
    const void*  obs_raw        = d_in[2];
    const void*  smask_raw      = d_in[3];
    const float* preh           = (const float*)d_in[4];

    const int base = (n_in >= 22) ? 6 : 5;
    const float* Wst  = (const float*)d_in[base + 0];   const float* bst  = (const float*)d_in[base + 1];
    const float* Wr   = (const float*)d_in[base + 2];   const float* br   = (const float*)d_in[base + 3];
    const float* Wq   = (const float*)d_in[base + 4];   const float* bq   = (const float*)d_in[base + 5];
    const float* Wk   = (const float*)d_in[base + 6];   const float* bk   = (const float*)d_in[base + 7];
    const float* Wv   = (const float*)d_in[base + 8];   const float* bv   = (const float*)d_in[base + 9];
    const float* Wih  = (const float*)d_in[base + 10];  const float* bih  = (const float*)d_in[base + 11];
    const float* Whh  = (const float*)d_in[base + 12];  const float* bhh  = (const float*)d_in[base + 13];
    const float* Wout = (const float*)d_in[base + 14];  const float* bout = (const float*)d_in[base + 15];

    float* params = (float*)d_out;
    float* hOut   = params + (size_t)M_AG * OUTD;

    float *KVb, *Qb, *gib, *ghb;
    float *stt, *emt, *pht, *att, *rwt, *ht;
    float *wstT, *wqT, *wkvT, *bkv, *wihT, *whhT, *woutT;
    unsigned char *obs, *smask;
    cudaGetSymbolAddress((void**)&KVb, g_KV);
    cudaGetSymbolAddress((void**)&Qb,  g_Q);
    cudaGetSymbolAddress((void**)&gib, g_gi);
    cudaGetSymbolAddress((void**)&ghb, g_gh);
    cudaGetSymbolAddress((void**)&stt, g_state_t);
    cudaGetSymbolAddress((void**)&emt, g_embed_t);
    cudaGetSymbolAddress((void**)&pht, g_preh_t);
    cudaGetSymbolAddress((void**)&att, g_att_t);
    cudaGetSymbolAddress((void**)&rwt, g_rew_t);
    cudaGetSymbolAddress((void**)&ht,  g_h_t);
    cudaGetSymbolAddress((void**)&wstT,  g_WstT);
    cudaGetSymbolAddress((void**)&wqT,   g_WqT);
    cudaGetSymbolAddress((void**)&wkvT,  g_WkvT);
    cudaGetSymbolAddress((void**)&bkv,   g_bkv);
    cudaGetSymbolAddress((void**)&wihT,  g_WihT);
    cudaGetSymbolAddress((void**)&whhT,  g_WhhT);
    cudaGetSymbolAddress((void**)&woutT, g_WoutT);
    cudaGetSymbolAddress((void**)&obs,   g_obs_u8);
    cudaGetSymbolAddress((void**)&smask, g_sm_u8);

    const int SM256 = GP<256>::SMEM;   // 196608
    const int SM128 = GP<128>::SMEM;   // 131072
    cudaFuncSetAttribute(gemm_tf32<256, MODE_DIR, EPI_RELU_RND>, cudaFuncAttributeMaxDynamicSharedMemorySize, SM256);
    cudaFuncSetAttribute(gemm_tf32<256, MODE_DIR, EPI_KV>,       cudaFuncAttributeMaxDynamicSharedMemorySize, SM256);
    cudaFuncSetAttribute(gemm_tf32<256, MODE_G16, EPI_F32>,      cudaFuncAttributeMaxDynamicSharedMemorySize, SM256);
    cudaFuncSetAttribute(gemm_tf32<256, MODE_CAT, EPI_F32>,      cudaFuncAttributeMaxDynamicSharedMemorySize, SM256);
    cudaFuncSetAttribute(gemm_tf32<256, MODE_DIR, EPI_F32>,      cudaFuncAttributeMaxDynamicSharedMemorySize, SM256);
    cudaFuncSetAttribute(gemm_tf32<128, MODE_DIR, EPI_MASK>,     cudaFuncAttributeMaxDynamicSharedMemorySize, SM128);

    dim3 blk(256);
    dim3 blk512(512);

    // 1. fused weight prep (+ mask-flag reset)
    prep_weights_kernel<<<(PREP_TOTAL + 255)/256, blk>>>(
        Wst, Wq, Wk, Wv, Wih, Whh, Wout, bk, bv);
    // 2. fused activation rounding
    conv_acts_kernel<<<(ACT_N4A + ACT_N4B + 255)/256, blk>>>(state, preh);

    // 3. embed = relu(state @ W_state + b), tf32-rounded output
    gemm_tf32<256, MODE_DIR, EPI_RELU_RND><<<dim3(HD/256, M_FULL/128), blk512, SM256>>>(
        stt, nullptr, nullptr, wstT, bst, emt, nullptr, DIN, HD);

    // 4. KV = embed @ [W_k|W_v] + [b_k|b_v], relu on V half    [ncu window]
    gemm_tf32<256, MODE_DIR, EPI_KV><<<dim3(2*AD/256, M_FULL/128), blk512, SM256>>>(
        emt, nullptr, nullptr, wkvT, bkv, KVb, nullptr, HD, 2*AD);

    // 5. Q = embed[:, :16 rows per batch] @ W_q + b            [ncu window]
    gemm_tf32<256, MODE_G16, EPI_F32><<<dim3(AD/256, M_AG/128), blk512, SM256>>>(
        emt, nullptr, nullptr, wqT, bq, Qb, nullptr, HD, AD);

    // 6. rew
    rew_kernel<<<(BSZ*RLD + 255)/256, blk>>>(prer, Wr, br, rwt);

    // 7-8. mask detection + conversion (needed only from attention onward)
    detect_mask_kernel<<<256, 256>>>((const unsigned int*)obs_raw, (BSZ*NE*NE)/4);
    convert_masks_kernel<<<(OBS4 + SM4 + 255)/256, blk>>>(obs_raw, smask_raw);

    // 9. attention (reads packed KV)
    attn_kernel<<<BSZ*NHD, 128>>>(Qb, KVb, obs, att);

    // 10. gi = concat(embed16, att, rew) @ W_ih + b, K=832
    gemm_tf32<256, MODE_CAT, EPI_F32><<<dim3(GID/256, M_AG/128), blk512, SM256>>>(
        emt, att, rwt, wihT, bih, gib, nullptr, HD + AD + RLD, GID);

    // 11. gh = pre_hidden @ W_hh + b
    gemm_tf32<256, MODE_DIR, EPI_F32><<<dim3(GID/256, M_AG/128), blk512, SM256>>>(
        pht, nullptr, nullptr, whhT, bhh, ghb, nullptr, HD, GID);

    // 12. GRU pointwise -> h
    gru_kernel<<<(M_AG*(HD/4) + 255)/256, blk>>>(gib, ghb, preh, smask, hOut, ht);

    // 13. params = h @ W_out + b, masked
    gemm_tf32<128, MODE_DIR, EPI_MASK><<<dim3(OUTD/128, M_AG/128), blk, SM128>>>(
        ht, nullptr, nullptr, woutT, bout, params, smask, HD, OUTD);
}

// round 14
// speedup vs baseline: 1.0259x; 1.0259x over previous
#include <cuda_runtime.h>
#include <cuda_bf16.h>
#include <math.h>
#include <stdint.h>

// ---------------- problem constants ----------------
#define BSZ     2048
#define NE      64
#define NA      16
#define DIN     128
#define HD      512
#define AD      256
#define NHD     8
#define ED      32
#define RLD     64
#define OUTD    128
#define M_FULL  (BSZ*NE)     // 131072
#define M_AG    (BSZ*NA)     // 32768
#define GID     1536         // 3*H

// ---------------- scratch (device globals; no allocs allowed) ----------------
__device__ __align__(256) float g_KV [(size_t)M_FULL*2*AD];
__device__ __align__(256) float g_Q  [(size_t)M_AG*AD];
__device__ __align__(256) float g_gi [(size_t)M_AG*GID];
__device__ __align__(256) float g_gh [(size_t)M_AG*GID];
__device__ __align__(256) float g_state_t[(size_t)M_FULL*DIN];
__device__ __align__(256) float g_embed_t[(size_t)M_FULL*HD];
__device__ __align__(256) float g_preh_t [(size_t)M_AG*HD];
__device__ __align__(256) float g_att_t  [(size_t)M_AG*AD];
__device__ __align__(256) float g_rew_t  [(size_t)BSZ*RLD];
__device__ __align__(256) float g_h_t    [(size_t)M_AG*HD];
__device__ __align__(256) float g_WstT [HD*DIN];
__device__ __align__(256) float g_WqT  [AD*HD];
__device__ __align__(256) float g_WkvT [2*AD*HD];
__device__ __align__(256) float g_bkv  [2*AD];
__device__ __align__(256) float g_WihT [GID*832];
__device__ __align__(256) float g_WhhT [GID*HD];
__device__ __align__(256) float g_WoutT[OUTD*HD];
__device__ unsigned char g_obs_u8[(size_t)BSZ*NE*NE];
__device__ unsigned char g_sm_u8 [(size_t)BSZ*NE];
__device__ int g_mask_flags;

// ---------------- baseline-PTX helpers ----------------
__device__ __forceinline__ uint32_t smem_u32(const void* p) {
    uint32_t a;
    asm("{ .reg .u64 t; cvta.to.shared.u64 t, %1; cvt.u32.u64 %0, t; }" : "=r"(a) : "l"(p));
    return a;
}
__device__ __forceinline__ void cp16(uint32_t dst, const void* src) {
    asm volatile("cp.async.cg.shared.global [%0], [%1], 16;" :: "r"(dst), "l"(src));
}
#define CP_COMMIT()  asm volatile("cp.async.commit_group;")
#define CP_WAIT(n)   asm volatile("cp.async.wait_group %0;" :: "n"(n))

__device__ __forceinline__ void ldm_x4(uint32_t* r, uint32_t addr) {
    asm volatile("ldmatrix.sync.aligned.m8n8.x4.shared.b16 {%0,%1,%2,%3}, [%4];"
                 : "=r"(r[0]), "=r"(r[1]), "=r"(r[2]), "=r"(r[3]) : "r"(addr));
}
__device__ __forceinline__ void mma_tf32(float* c, const uint32_t* a,
                                         uint32_t b0, uint32_t b1) {
    asm volatile(
        "mma.sync.aligned.m16n8k8.row.col.f32.tf32.tf32.f32 "
        "{%0,%1,%2,%3},{%4,%5,%6,%7},{%8,%9},{%0,%1,%2,%3};"
        : "+f"(c[0]), "+f"(c[1]), "+f"(c[2]), "+f"(c[3])
        : "r"(a[0]), "r"(a[1]), "r"(a[2]), "r"(a[3]), "r"(b0), "r"(b1));
}
__device__ __forceinline__ float rna_tf32(float v) {
    uint32_t r;
    asm("cvt.rna.tf32.f32 %0, %1;" : "=r"(r) : "f"(v));
    return __uint_as_float(r);
}

// ---------------- fused prep ----------------
#define PREP_TOTAL 2589184
__global__ void prep_weights_kernel(
    const float* __restrict__ Wst, const float* __restrict__ Wq,
    const float* __restrict__ Wk,  const float* __restrict__ Wv,
    const float* __restrict__ Wih, const float* __restrict__ Whh,
    const float* __restrict__ Wout,
    const float* __restrict__ bk,  const float* __restrict__ bv)
{
    int i = blockIdx.x * blockDim.x + threadIdx.x;
    if (i == 0) g_mask_flags = 0;
    if (i >= PREP_TOTAL) return;

    const float* src; float* dst; int K, N, j;
    if (i < 65536)        { j = i;           src = Wst;  dst = g_WstT;  K = DIN; N = HD; }
    else if (i < 196608)  { j = i - 65536;   src = Wq;   dst = g_WqT;   K = HD;  N = AD; }
    else if (i < 327680)  { j = i - 196608;  src = Wk;   dst = g_WkvT;  K = HD;  N = AD; }
    else if (i < 458752)  { j = i - 327680;  src = Wv;   dst = g_WkvT + AD*HD; K = HD; N = AD; }
    else if (i < 1736704) { j = i - 458752;  src = Wih;  dst = g_WihT;  K = 832; N = GID; }
    else if (i < 2523136) { j = i - 1736704; src = Whh;  dst = g_WhhT;  K = HD;  N = GID; }
    else if (i < 2588672) { j = i - 2523136; src = Wout; dst = g_WoutT; K = HD;  N = OUTD; }
    else {
        j = i - 2588672;
        g_bkv[j] = (j < AD) ? bk[j] : bv[j - AD];
        return;
    }
    int k = j / N, n = j % N;
    dst[(size_t)n * K + k] = rna_tf32(src[j]);
}

#define ACT_N4A (M_FULL*DIN/4)
#define ACT_N4B (M_AG*HD/4)
__global__ void conv_acts_kernel(const float* __restrict__ state,
                                 const float* __restrict__ preh)
{
    int i = blockIdx.x * blockDim.x + threadIdx.x;
    const float4* src; float4* dst; int j;
    if (i < ACT_N4A)                { j = i;           src = (const float4*)state; dst = (float4*)g_state_t; }
    else if (i < ACT_N4A + ACT_N4B) { j = i - ACT_N4A; src = (const float4*)preh;  dst = (float4*)g_preh_t; }
    else return;
    float4 v = src[j];
    v.x = rna_tf32(v.x); v.y = rna_tf32(v.y);
    v.z = rna_tf32(v.z); v.w = rna_tf32(v.w);
    dst[j] = v;
}

// ---------------- mask dtype detection + conversion ----------------
__global__ void detect_mask_kernel(const unsigned int* __restrict__ w, int nwords)
{
    int local = 0;
    for (int i = blockIdx.x * blockDim.x + threadIdx.x; i < nwords;
         i += gridDim.x * blockDim.x) {
        unsigned int v = w[i];
        if (v == 0x3F800000u) local |= 2;
        else if (v > 1u) local |= 1;
    }
    for (int d = 16; d > 0; d >>= 1) local |= __shfl_xor_sync(0xffffffffu, local, d);
    if ((threadIdx.x & 31) == 0 && local) atomicOr(&g_mask_flags, local);
}

#define OBS4 (BSZ*NE*NE/4)
#define SM4  (BSZ*NE/4)
__device__ __forceinline__ void conv4(const void* __restrict__ src,
                                      unsigned char* __restrict__ dst,
                                      int i, int mode)
{
    uchar4 o;
    if (mode == 1) {
        uchar4 v = ((const uchar4*)src)[i];
        o = make_uchar4(v.x != 0, v.y != 0, v.z != 0, v.w != 0);
    } else {
        uint4 v = ((const uint4*)src)[i];
        o = make_uchar4(v.x != 0, v.y != 0, v.z != 0, v.w != 0);
    }
    ((uchar4*)dst)[i] = o;
}
__global__ void convert_masks_kernel(const void* __restrict__ obs_src,
                                     const void* __restrict__ sm_src)
{
    int i = blockIdx.x * blockDim.x + threadIdx.x;
    int f = g_mask_flags;
    int mode = (f & 2) ? 2 : ((f & 1) ? 1 : 0);
    if (i < OBS4)            conv4(obs_src, g_obs_u8, i, mode);
    else if (i < OBS4 + SM4) conv4(sm_src,  g_sm_u8,  i - OBS4, mode);
}

// ---------------- tf32 HMMA GEMM core (round-12 best config) ----------------
// 256 threads. BN=256: warps 2(M)x4(N), MT=4. BN=128: warps 4(M)x2(N), MT=2.
enum { MODE_DIR = 0, MODE_G16 = 1, MODE_CAT = 2 };
enum { EPI_F32 = 0, EPI_RELU = 1, EPI_MASK = 2, EPI_RELU_RND = 3, EPI_KV = 4 };

template<int BN> struct GP {
    static const int STAGE_ROWS = 128 + BN;
    static const int STAGE_SZ   = STAGE_ROWS * 128;
    static const int SMEM       = 4 * STAGE_SZ;
    static const int WARPS_M    = (BN == 256) ? 2 : 4;
    static const int MT         = 8 / WARPS_M;
};

template<int MODE>
__device__ __forceinline__ const float* a_src(const float* A, const float* A2, const float* A3,
                                              int m, int K, int k0)
{
    if (MODE == MODE_CAT) {
        if (k0 < 512) return A  + (size_t)((m >> 4) * 64 + (m & 15)) * 512 + k0;
        if (k0 < 768) return A2 + (size_t)m * 256 + (k0 - 512);
        return A3 + (size_t)(m >> 4) * 64 + (k0 - 768);
    } else if (MODE == MODE_G16) {
        return A + (size_t)((m >> 4) * 64 + (m & 15)) * K + k0;
    } else {
        return A + (size_t)m * K + k0;
    }
}

template<int BN, int MODE, int EPI>
__device__ __forceinline__ void gemm_core(
    const float* __restrict__ A, const float* __restrict__ A2,
    const float* __restrict__ A3, const float* __restrict__ B,
    const float* __restrict__ bias, float* __restrict__ C,
    const unsigned char* __restrict__ smask,
    int K, int ldc, int bm, int bn, char* sm)
{
    const uint32_t smb = smem_u32(sm);
    const int tid  = threadIdx.x;
    const int wid  = tid >> 5;
    const int lane = tid & 31;

    const int warp_m = wid % GP<BN>::WARPS_M;
    const int warp_n = wid / GP<BN>::WARPS_M;
    const int MT = GP<BN>::MT;

    float acc[GP<BN>::MT][8][4];
    #pragma unroll
    for (int mt = 0; mt < GP<BN>::MT; mt++)
        #pragma unroll
        for (int nt = 0; nt < 8; nt++)
            #pragma unroll
            for (int r = 0; r < 4; r++) acc[mt][nt][r] = 0.0f;

    const int nch = K / 32;

    auto load_stage = [&](int s, int k0) {
        const uint32_t stg = smb + s * GP<BN>::STAGE_SZ;
        const int iters = GP<BN>::STAGE_ROWS * 8 / 256;
        #pragma unroll
        for (int it = 0; it < iters; it++) {
            int idx  = tid + it * 256;
            int grow = idx >> 3;
            int c16  = idx & 7;
            uint32_t dst = stg + grow * 128 + (uint32_t)((c16 ^ (grow & 7)) * 16);
            const float* src;
            if (grow < 128) src = a_src<MODE>(A, A2, A3, bm + grow, K, k0) + c16 * 4;
            else            src = B + (size_t)(bn + grow - 128) * K + k0 + c16 * 4;
            cp16(dst, src);
        }
    };

    load_stage(0, 0);
    CP_COMMIT();
    if (nch > 1) { load_stage(1, 32); CP_COMMIT(); }
    if (nch > 2) { load_stage(2, 64); CP_COMMIT(); }

    const int T = lane >> 3;
    const int tr = lane & 7;

    for (int c = 0; c < nch; c++) {
        const int rem = nch - 1 - c;
        if (rem >= 2)      { CP_WAIT(2); }
        else if (rem == 1) { CP_WAIT(1); }
        else               { CP_WAIT(0); }
        __syncthreads();

        const uint32_t stg = smb + (c & 3) * GP<BN>::STAGE_SZ;
        #pragma unroll
        for (int s = 0; s < 4; s++) {
            uint32_t a[GP<BN>::MT][4];
            #pragma unroll
            for (int mt = 0; mt < GP<BN>::MT; mt++) {
                uint32_t row = warp_m * (MT * 16) + mt * 16 + (T & 1) * 8 + tr;
                uint32_t chk = 2 * s + (T >> 1);
                ldm_x4(a[mt], stg + row * 128 + ((chk ^ (row & 7)) * 16));
            }
            #pragma unroll
            for (int nq = 0; nq < 4; nq++) {
                uint32_t nrow = 128 + warp_n * 64 + nq * 16 + (T >> 1) * 8 + tr;
                uint32_t chk = 2 * s + (T & 1);
                uint32_t b[4];
                ldm_x4(b, stg + nrow * 128 + ((chk ^ (nrow & 7)) * 16));
                #pragma unroll
                for (int mt = 0; mt < GP<BN>::MT; mt++) {
                    mma_tf32(acc[mt][nq * 2 + 0], a[mt], b[0], b[1]);
                    mma_tf32(acc[mt][nq * 2 + 1], a[mt], b[2], b[3]);
                }
            }
        }

        if (c + 3 < nch) {
            load_stage((c + 3) & 3, (c + 3) * 32);
            CP_COMMIT();
        }
    }

    #pragma unroll
    for (int mt = 0; mt < GP<BN>::MT; mt++) {
        #pragma unroll
        for (int nt = 0; nt < 8; nt++) {
            const int row0 = bm + warp_m * (MT * 16) + mt * 16 + (lane >> 2);
            const int col  = bn + warp_n * 64 + nt * 8 + (lane & 3) * 2;
            const float b0 = bias[col], b1 = bias[col + 1];
            #pragma unroll
            for (int h = 0; h < 2; h++) {
                const int row = row0 + h * 8;
                float v0 = acc[mt][nt][h * 2 + 0] + b0;
                float v1 = acc[mt][nt][h * 2 + 1] + b1;
                if (EPI == EPI_RELU || EPI == EPI_RELU_RND) {
                    v0 = fmaxf(v0, 0.0f); v1 = fmaxf(v1, 0.0f);
                }
                if (EPI == EPI_KV && col >= AD) {
                    v0 = fmaxf(v0, 0.0f); v1 = fmaxf(v1, 0.0f);
                }
                if (EPI == EPI_MASK) {
                    const int b = row >> 4, q = row & 15;
                    const float keep = smask[b * 64 + q] ? 0.0f : 1.0f;
                    v0 *= keep; v1 *= keep;
                }
                if (EPI == EPI_RELU_RND) { v0 = rna_tf32(v0); v1 = rna_tf32(v1); }
                *(float2*)(C + (size_t)row * ldc + col) = make_float2(v0, v1);
            }
        }
    }
}

// ---------------- GEMM kernels ----------------
// embed: plain BN=256 DIR/RELU_RND
__global__ void __launch_bounds__(256, 1)
gemm_embed(const float* __restrict__ A, const float* __restrict__ B,
           const float* __restrict__ bias, float* __restrict__ C)
{
    extern __shared__ char sm[];
    gemm_core<256, MODE_DIR, EPI_RELU_RND>(A, nullptr, nullptr, B, bias, C,
        nullptr, DIN, HD, blockIdx.y * 128, blockIdx.x * 256, sm);
}

// merged KV (z=0) + Q (z=1)
__global__ void __launch_bounds__(256, 1)
gemm_kvq(const float* __restrict__ emt,
         const float* __restrict__ wkvT, const float* __restrict__ bkv,
         float* __restrict__ KVb,
         const float* __restrict__ wqT, const float* __restrict__ bq,
         float* __restrict__ Qb)
{
    extern __shared__ char sm[];
    if (blockIdx.z == 0) {
        gemm_core<256, MODE_DIR, EPI_KV>(emt, nullptr, nullptr, wkvT, bkv, KVb,
            nullptr, HD, 2*AD, blockIdx.y * 128, blockIdx.x * 256, sm);
    } else {
        if (blockIdx.x >= 1 || blockIdx.y >= (M_AG/128)) return;
        gemm_core<256, MODE_G16, EPI_F32>(emt, nullptr, nullptr, wqT, bq, Qb,
            nullptr, HD, AD, blockIdx.y * 128, blockIdx.x * 256, sm);
    }
}

// merged gi (z=0, CAT K=832) + gh (z=1, DIR K=512)
__global__ void __launch_bounds__(256, 1)
gemm_gigh(const float* __restrict__ emt, const float* __restrict__ att,
          const float* __restrict__ rwt,
          const float* __restrict__ wihT, const float* __restrict__ bih,
          float* __restrict__ gib,
          const float* __restrict__ pht,
          const float* __restrict__ whhT, const float* __restrict__ bhh,
          float* __restrict__ ghb)
{
    extern __shared__ char sm[];
    if (blockIdx.z == 0) {
        gemm_core<256, MODE_CAT, EPI_F32>(emt, att, rwt, wihT, bih, gib,
            nullptr, HD + AD + RLD, GID, blockIdx.y * 128, blockIdx.x * 256, sm);
    } else {
        gemm_core<256, MODE_DIR, EPI_F32>(pht, nullptr, nullptr, whhT, bhh, ghb,
            nullptr, HD, GID, blockIdx.y * 128, blockIdx.x * 256, sm);
    }
}

// output GEMM: BN=128, masked
__global__ void __launch_bounds__(256, 1)
gemm_out(const float* __restrict__ ht, const float* __restrict__ woutT,
         const float* __restrict__ bout, float* __restrict__ params,
         const unsigned char* __restrict__ smask)
{
    extern __shared__ char sm[];
    gemm_core<128, MODE_DIR, EPI_MASK>(ht, nullptr, nullptr, woutT, bout, params,
        smask, HD, OUTD, blockIdx.y * 128, blockIdx.x * 128, sm);
}

// ---------------- reward projection ----------------
__global__ void rew_kernel(const float* __restrict__ prer,
                           const float* __restrict__ Wr,
                           const float* __restrict__ br,
                           float* __restrict__ out)
{
    int idx = blockIdx.x * blockDim.x + threadIdx.x;
    if (idx >= BSZ * RLD) return;
    int b = idx >> 6, j = idx & 63;
    out[idx] = rna_tf32(fmaxf(fmaf(prer[b], Wr[j], br[j]), 0.0f));
}

// ---------------- attention ----------------
__global__ void __launch_bounds__(128)
attn_kernel(const float* __restrict__ Qg, const float* __restrict__ KVg,
            const unsigned char* __restrict__ obs, float* __restrict__ outT)
{
    const int b = blockIdx.x >> 3;
    const int h = blockIdx.x & 7;
    const int tid = threadIdx.x;

    __shared__ float Qs[16][32];
    __shared__ float Ks[64][33];
    __shared__ float Vs[64][32];
    __shared__ float Ws[16][68];

    {
        int q = tid >> 3;
        int e4 = (tid & 7) * 4;
        *(float4*)&Qs[q][e4] =
            *(const float4*)(Qg + (size_t)(b * 16 + q) * 256 + h * 32 + e4);
    }
    #pragma unroll
    for (int i = 0; i < 4; i++) {
        int idx = tid + i * 128;
        int k = idx >> 3;
        int e4 = (idx & 7) * 4;
        const float* kvrow = KVg + (size_t)(b * 64 + k) * 512 + h * 32 + e4;
        float4 kv = *(const float4*)kvrow;
        Ks[k][e4 + 0] = kv.x; Ks[k][e4 + 1] = kv.y;
        Ks[k][e4 + 2] = kv.z; Ks[k][e4 + 3] = kv.w;
        *(float4*)&Vs[k][e4] = *(const float4*)(kvrow + 256);
    }
    __syncthreads();

    const float scale = 0.17677669529663687f;
    #pragma unroll
    for (int i = 0; i < 8; i++) {
        int s = tid + i * 128;
        int q = s >> 6;
        int k = s & 63;
        bool masked = (k == q) || (obs[(size_t)b * 4096 + q * 64 + k] != 0);
        float d;
        if (!masked) {
            d = 0.0f;
            #pragma unroll
            for (int e = 0; e < 32; e++) d = fmaf(Qs[q][e], Ks[k][e], d);
            d *= scale;
        } else {
            d = -INFINITY;
        }
        Ws[q][k] = d;
    }
    __syncthreads();

    {
        int q = tid >> 3;
        int l = tid & 7;
        float vals[8];
        float mx = -INFINITY;
        #pragma unroll
        for (int i = 0; i < 8; i++) { vals[i] = Ws[q][l + i * 8]; mx = fmaxf(mx, vals[i]); }
        #pragma unroll
        for (int d2 = 4; d2 > 0; d2 >>= 1) mx = fmaxf(mx, __shfl_xor_sync(0xffffffffu, mx, d2, 8));
        if (mx == -INFINITY) {
            #pragma unroll
            for (int i = 0; i < 8; i++) vals[i] = 0.0f;
        } else {
            float sum = 0.0f;
            #pragma unroll
            for (int i = 0; i < 8; i++) { vals[i] = __expf(vals[i] - mx); sum += vals[i]; }
            #pragma unroll
            for (int d2 = 4; d2 > 0; d2 >>= 1) sum += __shfl_xor_sync(0xffffffffu, sum, d2, 8);
            float inv = 1.0f / sum;
            #pragma unroll
            for (int i = 0; i < 8; i++) vals[i] *= inv;
        }
        #pragma unroll
        for (int i = 0; i < 8; i++) Ws[q][l + i * 8] = vals[i];
    }
    __syncthreads();

    #pragma unroll
    for (int i = 0; i < 4; i++) {
        int o = tid + i * 128;
        int q = o >> 5;
        int e = o & 31;
        float acc = 0.0f;
        #pragma unroll
        for (int k = 0; k < 64; k++) acc = fmaf(Ws[q][k], Vs[k][e], acc);
        outT[(size_t)(b * 16 + q) * 256 + h * 32 + e] = rna_tf32(acc);
    }
}

// ---------------- GRU pointwise ----------------
__device__ __forceinline__ float sigmoidf_(float x) { return 1.0f / (1.0f + __expf(-x)); }

__global__ void gru_kernel(const float* __restrict__ gi, const float* __restrict__ gh,
                           const float* __restrict__ preh,
                           const unsigned char* __restrict__ smask,
                           float* __restrict__ hOut, float* __restrict__ hT)
{
    int t = blockIdx.x * blockDim.x + threadIdx.x;
    if (t >= M_AG * (HD / 4)) return;
    int m  = t >> 7;
    int j4 = (t & 127) * 4;
    size_t gb = (size_t)m * GID + j4;
    size_t hb = (size_t)m * HD + j4;

    float4 ir = *(const float4*)(gi + gb);
    float4 iz = *(const float4*)(gi + gb + 512);
    float4 in = *(const float4*)(gi + gb + 1024);
    float4 hr = *(const float4*)(gh + gb);
    float4 hz = *(const float4*)(gh + gb + 512);
    float4 hn = *(const float4*)(gh + gb + 1024);
    float4 hp = *(const float4*)(preh + hb);

    int b = m >> 4, q = m & 15;
    float keep = smask[b * 64 + q] ? 0.0f : 1.0f;

    float o[4];
    {
        float r = sigmoidf_(ir.x + hr.x), z = sigmoidf_(iz.x + hz.x);
        float n = tanhf(in.x + r * hn.x);
        o[0] = keep * ((1.0f - z) * n + z * hp.x);
    }
    {
        float r = sigmoidf_(ir.y + hr.y), z = sigmoidf_(iz.y + hz.y);
        float n = tanhf(in.y + r * hn.y);
        o[1] = keep * ((1.0f - z) * n + z * hp.y);
    }
    {
        float r = sigmoidf_(ir.z + hr.z), z = sigmoidf_(iz.z + hz.z);
        float n = tanhf(in.z + r * hn.z);
        o[2] = keep * ((1.0f - z) * n + z * hp.z);
    }
    {
        float r = sigmoidf_(ir.w + hr.w), z = sigmoidf_(iz.w + hz.w);
        float n = tanhf(in.w + r * hn.w);
        o[3] = keep * ((1.0f - z) * n + z * hp.w);
    }
    *(float4*)(hOut + hb) = make_float4(o[0], o[1], o[2], o[3]);
    *(float4*)(hT + hb) = make_float4(rna_tf32(o[0]), rna_tf32(o[1]),
                                      rna_tf32(o[2]), rna_tf32(o[3]));
}

// ---------------- launch ----------------
extern "C" void kernel_launch(void* const* d_in, const int* in_sizes, int n_in,
                              void* d_out, int out_size)
{
    (void)in_sizes; (void)out_size;

    const float* state          = (const float*)d_in[0];
    const float* prer           = (const float*)d_in[1];
    const void*  obs_raw        = d_in[2];
    const void*  smask_raw      = d_in[3];
    const float* preh           = (const float*)d_in[4];

    const int base = (n_in >= 22) ? 6 : 5;
    const float* Wst  = (const float*)d_in[base + 0];   const float* bst  = (const float*)d_in[base + 1];
    const float* Wr   = (const float*)d_in[base + 2];   const float* br   = (const float*)d_in[base + 3];
    const float* Wq   = (const float*)d_in[base + 4];   const float* bq   = (const float*)d_in[base + 5];
    const float* Wk   = (const float*)d_in[base + 6];   const float* bk   = (const float*)d_in[base + 7];
    const float* Wv   = (const float*)d_in[base + 8];   const float* bv   = (const float*)d_in[base + 9];
    const float* Wih  = (const float*)d_in[base + 10];  const float* bih  = (const float*)d_in[base + 11];
    const float* Whh  = (const float*)d_in[base + 12];  const float* bhh  = (const float*)d_in[base + 13];
    const float* Wout = (const float*)d_in[base + 14];  const float* bout = (const float*)d_in[base + 15];

    float* params = (float*)d_out;
    float* hOut   = params + (size_t)M_AG * OUTD;

    float *KVb, *Qb, *gib, *ghb;
    float *stt, *emt, *pht, *att, *rwt, *ht;
    float *wstT, *wqT, *wkvT, *bkv, *wihT, *whhT, *woutT;
    unsigned char *obs, *smask;
    cudaGetSymbolAddress((void**)&KVb, g_KV);
    cudaGetSymbolAddress((void**)&Qb,  g_Q);
    cudaGetSymbolAddress((void**)&gib, g_gi);
    cudaGetSymbolAddress((void**)&ghb, g_gh);
    cudaGetSymbolAddress((void**)&stt, g_state_t);
    cudaGetSymbolAddress((void**)&emt, g_embed_t);
    cudaGetSymbolAddress((void**)&pht, g_preh_t);
    cudaGetSymbolAddress((void**)&att, g_att_t);
    cudaGetSymbolAddress((void**)&rwt, g_rew_t);
    cudaGetSymbolAddress((void**)&ht,  g_h_t);
    cudaGetSymbolAddress((void**)&wstT,  g_WstT);
    cudaGetSymbolAddress((void**)&wqT,   g_WqT);
    cudaGetSymbolAddress((void**)&wkvT,  g_WkvT);
    cudaGetSymbolAddress((void**)&bkv,   g_bkv);
    cudaGetSymbolAddress((void**)&wihT,  g_WihT);
    cudaGetSymbolAddress((void**)&whhT,  g_WhhT);
    cudaGetSymbolAddress((void**)&woutT, g_WoutT);
    cudaGetSymbolAddress((void**)&obs,   g_obs_u8);
    cudaGetSymbolAddress((void**)&smask, g_sm_u8);

    const int SM256 = GP<256>::SMEM;   // 196608
    const int SM128 = GP<128>::SMEM;   // 131072
    cudaFuncSetAttribute(gemm_embed, cudaFuncAttributeMaxDynamicSharedMemorySize, SM256);
    cudaFuncSetAttribute(gemm_kvq,   cudaFuncAttributeMaxDynamicSharedMemorySize, SM256);
    cudaFuncSetAttribute(gemm_gigh,  cudaFuncAttributeMaxDynamicSharedMemorySize, SM256);
    cudaFuncSetAttribute(gemm_out,   cudaFuncAttributeMaxDynamicSharedMemorySize, SM128);

    dim3 blk(256);

    // 1. fused weight prep (+ mask-flag reset)
    prep_weights_kernel<<<(PREP_TOTAL + 255)/256, blk>>>(
        Wst, Wq, Wk, Wv, Wih, Whh, Wout, bk, bv);
    // 2. fused activation rounding
    conv_acts_kernel<<<(ACT_N4A + ACT_N4B + 255)/256, blk>>>(state, preh);

    // 3. embed = relu(state @ W_state + b), tf32-rounded output
    gemm_embed<<<dim3(HD/256, M_FULL/128), blk, SM256>>>(stt, wstT, bst, emt);

    // 4. merged KV + Q GEMMs                                   [ncu window]
    gemm_kvq<<<dim3(2*AD/256, M_FULL/128, 2), blk, SM256>>>(
        emt, wkvT, bkv, KVb, wqT, bq, Qb);

    // 5. rew
    rew_kernel<<<(BSZ*RLD + 255)/256, blk>>>(prer, Wr, br, rwt);

    // 6-7. mask detection + conversion
    detect_mask_kernel<<<256, 256>>>((const unsigned int*)obs_raw, (BSZ*NE*NE)/4);
    convert_masks_kernel<<<(OBS4 + SM4 + 255)/256, blk>>>(obs_raw, smask_raw);

    // 8. attention (reads packed KV)
    attn_kernel<<<BSZ*NHD, 128>>>(Qb, KVb, obs, att);

    // 9. merged gi + gh GEMMs
    gemm_gigh<<<dim3(GID/256, M_AG/128, 2), blk, SM256>>>(
        emt, att, rwt, wihT, bih, gib, pht, whhT, bhh, ghb);

    // 10. GRU pointwise -> h
    gru_kernel<<<(M_AG*(HD/4) + 255)/256, blk>>>(gib, ghb, preh, smask, hOut, ht);

    // 11. params = h @ W_out + b, masked
    gemm_out<<<dim3(OUTD/128, M_AG/128), blk, SM128>>>(ht, woutT, bout, params, smask);
}

// round 15
// speedup vs baseline: 1.0365x; 1.0104x over previous
#include <cuda_runtime.h>
#include <cuda_bf16.h>
#include <math.h>
#include <stdint.h>

// ---------------- problem constants ----------------
#define BSZ     2048
#define NE      64
#define NA      16
#define DIN     128
#define HD      512
#define AD      256
#define NHD     8
#define ED      32
#define RLD     64
#define OUTD    128
#define M_FULL  (BSZ*NE)     // 131072
#define M_AG    (BSZ*NA)     // 32768
#define GID     1536         // 3*H

// ---------------- scratch (device globals; no allocs allowed) ----------------
__device__ __align__(256) float g_KV [(size_t)M_FULL*2*AD];
__device__ __align__(256) float g_Q  [(size_t)M_AG*AD];
__device__ __align__(256) float g_gi [(size_t)M_AG*GID];
__device__ __align__(256) float g_gh [(size_t)M_AG*GID];
__device__ __align__(256) float g_state_t[(size_t)M_FULL*DIN];
__device__ __align__(256) float g_embed_t[(size_t)M_FULL*HD];
__device__ __align__(256) float g_preh_t [(size_t)M_AG*HD];
__device__ __align__(256) float g_att_t  [(size_t)M_AG*AD];
__device__ __align__(256) float g_rew_t  [(size_t)BSZ*RLD];
__device__ __align__(256) float g_h_t    [(size_t)M_AG*HD];
__device__ __align__(256) float g_WstT [HD*DIN];
__device__ __align__(256) float g_WqT  [AD*HD];
__device__ __align__(256) float g_WkvT [2*AD*HD];
__device__ __align__(256) float g_bkv  [2*AD];
__device__ __align__(256) float g_WihT [GID*832];
__device__ __align__(256) float g_WhhT [GID*HD];
__device__ __align__(256) float g_WoutT[OUTD*HD];
__device__ unsigned char g_obs_u8[(size_t)BSZ*NE*NE];
__device__ unsigned char g_sm_u8 [(size_t)BSZ*NE];
__device__ int g_mask_flags;

// ---------------- baseline-PTX helpers ----------------
__device__ __forceinline__ uint32_t smem_u32(const void* p) {
    uint32_t a;
    asm("{ .reg .u64 t; cvta.to.shared.u64 t, %1; cvt.u32.u64 %0, t; }" : "=r"(a) : "l"(p));
    return a;
}
__device__ __forceinline__ void cp16(uint32_t dst, const void* src) {
    asm volatile("cp.async.cg.shared.global [%0], [%1], 16;" :: "r"(dst), "l"(src));
}
#define CP_COMMIT()  asm volatile("cp.async.commit_group;")
#define CP_WAIT(n)   asm volatile("cp.async.wait_group %0;" :: "n"(n))

__device__ __forceinline__ void ldm_x4(uint32_t* r, uint32_t addr) {
    asm volatile("ldmatrix.sync.aligned.m8n8.x4.shared.b16 {%0,%1,%2,%3}, [%4];"
                 : "=r"(r[0]), "=r"(r[1]), "=r"(r[2]), "=r"(r[3]) : "r"(addr));
}
__device__ __forceinline__ void mma_tf32(float* c, const uint32_t* a,
                                         uint32_t b0, uint32_t b1) {
    asm volatile(
        "mma.sync.aligned.m16n8k8.row.col.f32.tf32.tf32.f32 "
        "{%0,%1,%2,%3},{%4,%5,%6,%7},{%8,%9},{%0,%1,%2,%3};"
        : "+f"(c[0]), "+f"(c[1]), "+f"(c[2]), "+f"(c[3])
        : "r"(a[0]), "r"(a[1]), "r"(a[2]), "r"(a[3]), "r"(b0), "r"(b1));
}
__device__ __forceinline__ float rna_tf32(float v) {
    uint32_t r;
    asm("cvt.rna.tf32.f32 %0, %1;" : "=r"(r) : "f"(v));
    return __uint_as_float(r);
}

// ---------------- fused prep: weight transposes + bias concat + flag reset ----
#define PREP_TOTAL 2589184
__global__ void prep_weights_kernel(
    const float* __restrict__ Wst, const float* __restrict__ Wq,
    const float* __restrict__ Wk,  const float* __restrict__ Wv,
    const float* __restrict__ Wih, const float* __restrict__ Whh,
    const float* __restrict__ Wout,
    const float* __restrict__ bk,  const float* __restrict__ bv)
{
    int i = blockIdx.x * blockDim.x + threadIdx.x;
    if (i == 0) g_mask_flags = 0;
    if (i >= PREP_TOTAL) return;

    const float* src; float* dst; int K, N, j;
    if (i < 65536)        { j = i;           src = Wst;  dst = g_WstT;  K = DIN; N = HD; }
    else if (i < 196608)  { j = i - 65536;   src = Wq;   dst = g_WqT;   K = HD;  N = AD; }
    else if (i < 327680)  { j = i - 196608;  src = Wk;   dst = g_WkvT;  K = HD;  N = AD; }
    else if (i < 458752)  { j = i - 327680;  src = Wv;   dst = g_WkvT + AD*HD; K = HD; N = AD; }
    else if (i < 1736704) { j = i - 458752;  src = Wih;  dst = g_WihT;  K = 832; N = GID; }
    else if (i < 2523136) { j = i - 1736704; src = Whh;  dst = g_WhhT;  K = HD;  N = GID; }
    else if (i < 2588672) { j = i - 2523136; src = Wout; dst = g_WoutT; K = HD;  N = OUTD; }
    else {
        j = i - 2588672;
        g_bkv[j] = (j < AD) ? bk[j] : bv[j - AD];
        return;
    }
    int k = j / N, n = j % N;
    dst[(size_t)n * K + k] = rna_tf32(src[j]);
}

// ---------------- fused activations: round state+preh, rew proj, mask detect --
#define ACT_N4A (M_FULL*DIN/4)        // 4,194,304
#define ACT_N4B (M_AG*HD/4)           // 4,194,304
#define SEG_REW  (ACT_N4A + ACT_N4B)
#define REW_N    (BSZ*RLD)            // 131,072
#define SEG_DET  (SEG_REW + REW_N)
#define DET_WORDS (BSZ*NE*NE/4)       // 2,097,152 (safe for 1B and 4B encodings)
#define DET_N    (DET_WORDS/8)        // 262,144
#define ACT_TOTAL (SEG_DET + DET_N)
__global__ void conv_acts_kernel(const float* __restrict__ state,
                                 const float* __restrict__ preh,
                                 const float* __restrict__ prer,
                                 const float* __restrict__ Wr,
                                 const float* __restrict__ br,
                                 const unsigned int* __restrict__ obs_w)
{
    int i = blockIdx.x * blockDim.x + threadIdx.x;
    if (i < ACT_N4A + ACT_N4B) {
        const float4* src; float4* dst; int j;
        if (i < ACT_N4A) { j = i;           src = (const float4*)state; dst = (float4*)g_state_t; }
        else             { j = i - ACT_N4A; src = (const float4*)preh;  dst = (float4*)g_preh_t; }
        float4 v = src[j];
        v.x = rna_tf32(v.x); v.y = rna_tf32(v.y);
        v.z = rna_tf32(v.z); v.w = rna_tf32(v.w);
        dst[j] = v;
    } else if (i < SEG_DET) {
        int idx = i - SEG_REW;                 // rew projection
        int b = idx >> 6, j = idx & 63;
        g_rew_t[idx] = rna_tf32(fmaxf(fmaf(prer[b], Wr[j], br[j]), 0.0f));
    } else if (i < ACT_TOTAL) {
        int j = (i - SEG_DET) * 8;             // mask dtype detection, 8 words/thread
        int local = 0;
        #pragma unroll
        for (int w = 0; w < 8; w++) {
            unsigned int v = obs_w[j + w];
            if (v == 0x3F800000u) local |= 2;
            else if (v > 1u) local |= 1;
        }
        if (local & ~g_mask_flags) atomicOr(&g_mask_flags, local);
    }
}

// ---------------- fused vectorized mask conversion ----------------
#define OBS4 (BSZ*NE*NE/4)
#define SM4  (BSZ*NE/4)
__device__ __forceinline__ void conv4(const void* __restrict__ src,
                                      unsigned char* __restrict__ dst,
                                      int i, int mode)
{
    uchar4 o;
    if (mode == 1) {
        uchar4 v = ((const uchar4*)src)[i];
        o = make_uchar4(v.x != 0, v.y != 0, v.z != 0, v.w != 0);
    } else {
        uint4 v = ((const uint4*)src)[i];
        o = make_uchar4(v.x != 0, v.y != 0, v.z != 0, v.w != 0);
    }
    ((uchar4*)dst)[i] = o;
}
__global__ void convert_masks_kernel(const void* __restrict__ obs_src,
                                     const void* __restrict__ sm_src)
{
    int i = blockIdx.x * blockDim.x + threadIdx.x;
    int f = g_mask_flags;
    int mode = (f & 2) ? 2 : ((f & 1) ? 1 : 0);
    if (i < OBS4)            conv4(obs_src, g_obs_u8, i, mode);
    else if (i < OBS4 + SM4) conv4(sm_src,  g_sm_u8,  i - OBS4, mode);
}

// ---------------- tf32 HMMA GEMM core (measured-best config) ----------------
enum { MODE_DIR = 0, MODE_G16 = 1, MODE_CAT = 2 };
enum { EPI_F32 = 0, EPI_RELU = 1, EPI_MASK = 2, EPI_RELU_RND = 3, EPI_KV = 4 };

template<int BN> struct GP {
    static const int STAGE_ROWS = 128 + BN;
    static const int STAGE_SZ   = STAGE_ROWS * 128;
    static const int SMEM       = 4 * STAGE_SZ;
    static const int WARPS_M    = (BN == 256) ? 2 : 4;
    static const int MT         = 8 / WARPS_M;
};

template<int MODE>
__device__ __forceinline__ const float* a_src(const float* A, const float* A2, const float* A3,
                                              int m, int K, int k0)
{
    if (MODE == MODE_CAT) {
        if (k0 < 512) return A  + (size_t)((m >> 4) * 64 + (m & 15)) * 512 + k0;
        if (k0 < 768) return A2 + (size_t)m * 256 + (k0 - 512);
        return A3 + (size_t)(m >> 4) * 64 + (k0 - 768);
    } else if (MODE == MODE_G16) {
        return A + (size_t)((m >> 4) * 64 + (m & 15)) * K + k0;
    } else {
        return A + (size_t)m * K + k0;
    }
}

template<int BN, int MODE, int EPI>
__device__ __forceinline__ void gemm_core(
    const float* __restrict__ A, const float* __restrict__ A2,
    const float* __restrict__ A3, const float* __restrict__ B,
    const float* __restrict__ bias, float* __restrict__ C,
    const unsigned char* __restrict__ smask,
    int K, int ldc, int bm, int bn, char* sm)
{
    const uint32_t smb = smem_u32(sm);
    const int tid  = threadIdx.x;
    const int wid  = tid >> 5;
    const int lane = tid & 31;

    const int warp_m = wid % GP<BN>::WARPS_M;
    const int warp_n = wid / GP<BN>::WARPS_M;
    const int MT = GP<BN>::MT;

    float acc[GP<BN>::MT][8][4];
    #pragma unroll
    for (int mt = 0; mt < GP<BN>::MT; mt++)
        #pragma unroll
        for (int nt = 0; nt < 8; nt++)
            #pragma unroll
            for (int r = 0; r < 4; r++) acc[mt][nt][r] = 0.0f;

    const int nch = K / 32;

    auto load_stage = [&](int s, int k0) {
        const uint32_t stg = smb + s * GP<BN>::STAGE_SZ;
        const int iters = GP<BN>::STAGE_ROWS * 8 / 256;
        #pragma unroll
        for (int it = 0; it < iters; it++) {
            int idx  = tid + it * 256;
            int grow = idx >> 3;
            int c16  = idx & 7;
            uint32_t dst = stg + grow * 128 + (uint32_t)((c16 ^ (grow & 7)) * 16);
            const float* src;
            if (grow < 128) src = a_src<MODE>(A, A2, A3, bm + grow, K, k0) + c16 * 4;
            else            src = B + (size_t)(bn + grow - 128) * K + k0 + c16 * 4;
            cp16(dst, src);
        }
    };

    load_stage(0, 0);
    CP_COMMIT();
    if (nch > 1) { load_stage(1, 32); CP_COMMIT(); }
    if (nch > 2) { load_stage(2, 64); CP_COMMIT(); }

    const int T = lane >> 3;
    const int tr = lane & 7;

    for (int c = 0; c < nch; c++) {
        const int rem = nch - 1 - c;
        if (rem >= 2)      { CP_WAIT(2); }
        else if (rem == 1) { CP_WAIT(1); }
        else               { CP_WAIT(0); }
        __syncthreads();

        const uint32_t stg = smb + (c & 3) * GP<BN>::STAGE_SZ;
        #pragma unroll
        for (int s = 0; s < 4; s++) {
            uint32_t a[GP<BN>::MT][4];
            #pragma unroll
            for (int mt = 0; mt < GP<BN>::MT; mt++) {
                uint32_t row = warp_m * (MT * 16) + mt * 16 + (T & 1) * 8 + tr;
                uint32_t chk = 2 * s + (T >> 1);
                ldm_x4(a[mt], stg + row * 128 + ((chk ^ (row & 7)) * 16));
            }
            #pragma unroll
            for (int nq = 0; nq < 4; nq++) {
                uint32_t nrow = 128 + warp_n * 64 + nq * 16 + (T >> 1) * 8 + tr;
                uint32_t chk = 2 * s + (T & 1);
                uint32_t b[4];
                ldm_x4(b, stg + nrow * 128 + ((chk ^ (nrow & 7)) * 16));
                #pragma unroll
                for (int mt = 0; mt < GP<BN>::MT; mt++) {
                    mma_tf32(acc[mt][nq * 2 + 0], a[mt], b[0], b[1]);
                    mma_tf32(acc[mt][nq * 2 + 1], a[mt], b[2], b[3]);
                }
            }
        }

        if (c + 3 < nch) {
            load_stage((c + 3) & 3, (c + 3) * 32);
            CP_COMMIT();
        }
    }

    #pragma unroll
    for (int mt = 0; mt < GP<BN>::MT; mt++) {
        #pragma unroll
        for (int nt = 0; nt < 8; nt++) {
            const int row0 = bm + warp_m * (MT * 16) + mt * 16 + (lane >> 2);
            const int col  = bn + warp_n * 64 + nt * 8 + (lane & 3) * 2;
            const float b0 = bias[col], b1 = bias[col + 1];
            #pragma unroll
            for (int h = 0; h < 2; h++) {
                const int row = row0 + h * 8;
                float v0 = acc[mt][nt][h * 2 + 0] + b0;
                float v1 = acc[mt][nt][h * 2 + 1] + b1;
                if (EPI == EPI_RELU || EPI == EPI_RELU_RND) {
                    v0 = fmaxf(v0, 0.0f); v1 = fmaxf(v1, 0.0f);
                }
                if (EPI == EPI_KV && col >= AD) {
                    v0 = fmaxf(v0, 0.0f); v1 = fmaxf(v1, 0.0f);
                }
                if (EPI == EPI_MASK) {
                    const int b = row >> 4, q = row & 15;
                    const float keep = smask[b * 64 + q] ? 0.0f : 1.0f;
                    v0 *= keep; v1 *= keep;
                }
                if (EPI == EPI_RELU_RND) { v0 = rna_tf32(v0); v1 = rna_tf32(v1); }
                *(float2*)(C + (size_t)row * ldc + col) = make_float2(v0, v1);
            }
        }
    }
}

// ---------------- GEMM kernels ----------------
__global__ void __launch_bounds__(256, 1)
gemm_embed(const float* __restrict__ A, const float* __restrict__ B,
           const float* __restrict__ bias, float* __restrict__ C)
{
    extern __shared__ char sm[];
    gemm_core<256, MODE_DIR, EPI_RELU_RND>(A, nullptr, nullptr, B, bias, C,
        nullptr, DIN, HD, blockIdx.y * 128, blockIdx.x * 256, sm);
}

__global__ void __launch_bounds__(256, 1)
gemm_kvq(const float* __restrict__ emt,
         const float* __restrict__ wkvT, const float* __restrict__ bkv,
         float* __restrict__ KVb,
         const float* __restrict__ wqT, const float* __restrict__ bq,
         float* __restrict__ Qb)
{
    extern __shared__ char sm[];
    if (blockIdx.z == 0) {
        gemm_core<256, MODE_DIR, EPI_KV>(emt, nullptr, nullptr, wkvT, bkv, KVb,
            nullptr, HD, 2*AD, blockIdx.y * 128, blockIdx.x * 256, sm);
    } else {
        if (blockIdx.x >= 1 || blockIdx.y >= (M_AG/128)) return;
        gemm_core<256, MODE_G16, EPI_F32>(emt, nullptr, nullptr, wqT, bq, Qb,
            nullptr, HD, AD, blockIdx.y * 128, blockIdx.x * 256, sm);
    }
}

__global__ void __launch_bounds__(256, 1)
gemm_gigh(const float* __restrict__ emt, const float* __restrict__ att,
          const float* __restrict__ rwt,
          const float* __restrict__ wihT, const float* __restrict__ bih,
          float* __restrict__ gib,
          const float* __restrict__ pht,
          const float* __restrict__ whhT, const float* __restrict__ bhh,
          float* __restrict__ ghb)
{
    extern __shared__ char sm[];
    if (blockIdx.z == 0) {
        gemm_core<256, MODE_CAT, EPI_F32>(emt, att, rwt, wihT, bih, gib,
            nullptr, HD + AD + RLD, GID, blockIdx.y * 128, blockIdx.x * 256, sm);
    } else {
        gemm_core<256, MODE_DIR, EPI_F32>(pht, nullptr, nullptr, whhT, bhh, ghb,
            nullptr, HD, GID, blockIdx.y * 128, blockIdx.x * 256, sm);
    }
}

__global__ void __launch_bounds__(256, 1)
gemm_out(const float* __restrict__ ht, const float* __restrict__ woutT,
         const float* __restrict__ bout, float* __restrict__ params,
         const unsigned char* __restrict__ smask)
{
    extern __shared__ char sm[];
    gemm_core<128, MODE_DIR, EPI_MASK>(ht, nullptr, nullptr, woutT, bout, params,
        smask, HD, OUTD, blockIdx.y * 128, blockIdx.x * 128, sm);
}

// ---------------- attention ----------------
__global__ void __launch_bounds__(128)
attn_kernel(const float* __restrict__ Qg, const float* __restrict__ KVg,
            const unsigned char* __restrict__ obs, float* __restrict__ outT)
{
    const int b = blockIdx.x >> 3;
    const int h = blockIdx.x & 7;
    const int tid = threadIdx.x;

    __shared__ float Qs[16][32];
    __shared__ float Ks[64][33];
    __shared__ float Vs[64][32];
    __shared__ float Ws[16][68];

    {
        int q = tid >> 3;
        int e4 = (tid & 7) * 4;
        *(float4*)&Qs[q][e4] =
            *(const float4*)(Qg + (size_t)(b * 16 + q) * 256 + h * 32 + e4);
    }
    #pragma unroll
    for (int i = 0; i < 4; i++) {
        int idx = tid + i * 128;
        int k = idx >> 3;
        int e4 = (idx & 7) * 4;
        const float* kvrow = KVg + (size_t)(b * 64 + k) * 512 + h * 32 + e4;
        float4 kv = *(const float4*)kvrow;
        Ks[k][e4 + 0] = kv.x; Ks[k][e4 + 1] = kv.y;
        Ks[k][e4 + 2] = kv.z; Ks[k][e4 + 3] = kv.w;
        *(float4*)&Vs[k][e4] = *(const float4*)(kvrow + 256);
    }
    __syncthreads();

    const float scale = 0.17677669529663687f;
    #pragma unroll
    for (int i = 0; i < 8; i++) {
        int s = tid + i * 128;
        int q = s >> 6;
        int k = s & 63;
        bool masked = (k == q) || (obs[(size_t)b * 4096 + q * 64 + k] != 0);
        float d;
        if (!masked) {
            d = 0.0f;
            #pragma unroll
            for (int e = 0; e < 32; e++) d = fmaf(Qs[q][e], Ks[k][e], d);
            d *= scale;
        } else {
            d = -INFINITY;
        }
        Ws[q][k] = d;
    }
    __syncthreads();

    {
        int q = tid >> 3;
        int l = tid & 7;
        float vals[8];
        float mx = -INFINITY;
        #pragma unroll
        for (int i = 0; i < 8; i++) { vals[i] = Ws[q][l + i * 8]; mx = fmaxf(mx, vals[i]); }
        #pragma unroll
        for (int d2 = 4; d2 > 0; d2 >>= 1) mx = fmaxf(mx, __shfl_xor_sync(0xffffffffu, mx, d2, 8));
        if (mx == -INFINITY) {
            #pragma unroll
            for (int i = 0; i < 8; i++) vals[i] = 0.0f;
        } else {
            float sum = 0.0f;
            #pragma unroll
            for (int i = 0; i < 8; i++) { vals[i] = __expf(vals[i] - mx); sum += vals[i]; }
            #pragma unroll
            for (int d2 = 4; d2 > 0; d2 >>= 1) sum += __shfl_xor_sync(0xffffffffu, sum, d2, 8);
            float inv = 1.0f / sum;
            #pragma unroll
            for (int i = 0; i < 8; i++) vals[i] *= inv;
        }
        #pragma unroll
        for (int i = 0; i < 8; i++) Ws[q][l + i * 8] = vals[i];
    }
    __syncthreads();

    #pragma unroll
    for (int i = 0; i < 4; i++) {
        int o = tid + i * 128;
        int q = o >> 5;
        int e = o & 31;
        float acc = 0.0f;
        #pragma unroll
        for (int k = 0; k < 64; k++) acc = fmaf(Ws[q][k], Vs[k][e], acc);
        outT[(size_t)(b * 16 + q) * 256 + h * 32 + e] = rna_tf32(acc);
    }
}

// ---------------- GRU pointwise ----------------
__device__ __forceinline__ float sigmoidf_(float x) { return 1.0f / (1.0f + __expf(-x)); }

__global__ void gru_kernel(const float* __restrict__ gi, const float* __restrict__ gh,
                           const float* __restrict__ preh,
                           const unsigned char* __restrict__ smask,
                           float* __restrict__ hOut, float* __restrict__ hT)
{
    int t = blockIdx.x * blockDim.x + threadIdx.x;
    if (t >= M_AG * (HD / 4)) return;
    int m  = t >> 7;
    int j4 = (t & 127) * 4;
    size_t gb = (size_t)m * GID + j4;
    size_t hb = (size_t)m * HD + j4;

    float4 ir = *(const float4*)(gi + gb);
    float4 iz = *(const float4*)(gi + gb + 512);
    float4 in = *(const float4*)(gi + gb + 1024);
    float4 hr = *(const float4*)(gh + gb);
    float4 hz = *(const float4*)(gh + gb + 512);
    float4 hn = *(const float4*)(gh + gb + 1024);
    float4 hp = *(const float4*)(preh + hb);

    int b = m >> 4, q = m & 15;
    float keep = smask[b * 64 + q] ? 0.0f : 1.0f;

    float o[4];
    {
        float r = sigmoidf_(ir.x + hr.x), z = sigmoidf_(iz.x + hz.x);
        float n = tanhf(in.x + r * hn.x);
        o[0] = keep * ((1.0f - z) * n + z * hp.x);
    }
    {
        float r = sigmoidf_(ir.y + hr.y), z = sigmoidf_(iz.y + hz.y);
        float n = tanhf(in.y + r * hn.y);
        o[1] = keep * ((1.0f - z) * n + z * hp.y);
    }
    {
        float r = sigmoidf_(ir.z + hr.z), z = sigmoidf_(iz.z + hz.z);
        float n = tanhf(in.z + r * hn.z);
        o[2] = keep * ((1.0f - z) * n + z * hp.z);
    }
    {
        float r = sigmoidf_(ir.w + hr.w), z = sigmoidf_(iz.w + hz.w);
        float n = tanhf(in.w + r * hn.w);
        o[3] = keep * ((1.0f - z) * n + z * hp.w);
    }
    *(float4*)(hOut + hb) = make_float4(o[0], o[1], o[2], o[3]);
    *(float4*)(hT + hb) = make_float4(rna_tf32(o[0]), rna_tf32(o[1]),
                                      rna_tf32(o[2]), rna_tf32(o[3]));
}

// ---------------- launch ----------------
extern "C" void kernel_launch(void* const* d_in, const int* in_sizes, int n_in,
                              void* d_out, int out_size)
{
    (void)in_sizes; (void)out_size;

    const float* state          = (const float*)d_in[0];
    const float* prer           = (const float*)d_in[1];
    const void*  obs_raw        = d_in[2];
    const void*  smask_raw      = d_in[3];
    const float* preh           = (const float*)d_in[4];

    const int base = (n_in >= 22) ? 6 : 5;
    const float* Wst  = (const float*)d_in[base + 0];   const float* bst  = (const float*)d_in[base + 1];
    const float* Wr   = (const float*)d_in[base + 2];   const float* br   = (const float*)d_in[base + 3];
    const float* Wq   = (const float*)d_in[base + 4];   const float* bq   = (const float*)d_in[base + 5];
    const float* Wk   = (const float*)d_in[base + 6];   const float* bk   = (const float*)d_in[base + 7];
    const float* Wv   = (const float*)d_in[base + 8];   const float* bv   = (const float*)d_in[base + 9];
    const float* Wih  = (const float*)d_in[base + 10];  const float* bih  = (const float*)d_in[base + 11];
    const float* Whh  = (const float*)d_in[base + 12];  const float* bhh  = (const float*)d_in[base + 13];
    const float* Wout = (const float*)d_in[base + 14];  const float* bout = (const float*)d_in[base + 15];

    float* params = (float*)d_out;
    float* hOut   = params + (size_t)M_AG * OUTD;

    float *KVb, *Qb, *gib, *ghb;
    float *stt, *emt, *pht, *att, *rwt, *ht;
    float *wstT, *wqT, *wkvT, *bkv, *wihT, *whhT, *woutT;
    unsigned char *obs, *smask;
    cudaGetSymbolAddress((void**)&KVb, g_KV);
    cudaGetSymbolAddress((void**)&Qb,  g_Q);
    cudaGetSymbolAddress((void**)&gib, g_gi);
    cudaGetSymbolAddress((void**)&ghb, g_gh);
    cudaGetSymbolAddress((void**)&stt, g_state_t);
    cudaGetSymbolAddress((void**)&emt, g_embed_t);
    cudaGetSymbolAddress((void**)&pht, g_preh_t);
    cudaGetSymbolAddress((void**)&att, g_att_t);
    cudaGetSymbolAddress((void**)&rwt, g_rew_t);
    cudaGetSymbolAddress((void**)&ht,  g_h_t);
    cudaGetSymbolAddress((void**)&wstT,  g_WstT);
    cudaGetSymbolAddress((void**)&wqT,   g_WqT);
    cudaGetSymbolAddress((void**)&wkvT,  g_WkvT);
    cudaGetSymbolAddress((void**)&bkv,   g_bkv);
    cudaGetSymbolAddress((void**)&wihT,  g_WihT);
    cudaGetSymbolAddress((void**)&whhT,  g_WhhT);
    cudaGetSymbolAddress((void**)&woutT, g_WoutT);
    cudaGetSymbolAddress((void**)&obs,   g_obs_u8);
    cudaGetSymbolAddress((void**)&smask, g_sm_u8);

    const int SM256 = GP<256>::SMEM;   // 196608
    const int SM128 = GP<128>::SMEM;   // 131072
    cudaFuncSetAttribute(gemm_embed, cudaFuncAttributeMaxDynamicSharedMemorySize, SM256);
    cudaFuncSetAttribute(gemm_kvq,   cudaFuncAttributeMaxDynamicSharedMemorySize, SM256);
    cudaFuncSetAttribute(gemm_gigh,  cudaFuncAttributeMaxDynamicSharedMemorySize, SM256);
    cudaFuncSetAttribute(gemm_out,   cudaFuncAttributeMaxDynamicSharedMemorySize, SM128);

    dim3 blk(256);

    // 1. fused weight prep (+ mask-flag reset)
    prep_weights_kernel<<<(PREP_TOTAL + 255)/256, blk>>>(
        Wst, Wq, Wk, Wv, Wih, Whh, Wout, bk, bv);

    // 2. fused: activation rounding + rew projection + mask dtype detection
    conv_acts_kernel<<<(ACT_TOTAL + 255)/256, blk>>>(
        state, preh, prer, Wr, br, (const unsigned int*)obs_raw);

    // 3. fused vectorized mask conversion
    convert_masks_kernel<<<(OBS4 + SM4 + 255)/256, blk>>>(obs_raw, smask_raw);

    // 4. embed = relu(state @ W_state + b), tf32-rounded output  [ncu window]
    gemm_embed<<<dim3(HD/256, M_FULL/128), blk, SM256>>>(stt, wstT, bst, emt);

    // 5. merged KV + Q GEMMs                                     [ncu window]
    gemm_kvq<<<dim3(2*AD/256, M_FULL/128, 2), blk, SM256>>>(
        emt, wkvT, bkv, KVb, wqT, bq, Qb);

    // 6. attention (reads packed KV)
    attn_kernel<<<BSZ*NHD, 128>>>(Qb, KVb, obs, att);

    // 7. merged gi + gh GEMMs
    gemm_gigh<<<dim3(GID/256, M_AG/128, 2), blk, SM256>>>(
        emt, att, rwt, wihT, bih, gib, pht, whhT, bhh, ghb);

    // 8. GRU pointwise -> h
    gru_kernel<<<(M_AG*(HD/4) + 255)/256, blk>>>(gib, ghb, preh, smask, hOut, ht);

    // 9. params = h @ W_out + b, masked
    gemm_out<<<dim3(OUTD/128, M_AG/128), blk, SM128>>>(ht, woutT, bout, params, smask);
}

// round 17
// speedup vs baseline: 1.0379x; 1.0013x over previous
#include <cuda_runtime.h>
#include <cuda_bf16.h>
#include <math.h>
#include <stdint.h>

// ---------------- problem constants ----------------
#define BSZ     2048
#define NE      64
#define NA      16
#define DIN     128
#define HD      512
#define AD      256
#define NHD     8
#define ED      32
#define RLD     64
#define OUTD    128
#define M_FULL  (BSZ*NE)     // 131072
#define M_AG    (BSZ*NA)     // 32768
#define GID     1536         // 3*H

// ---------------- scratch (device globals; no allocs allowed) ----------------
__device__ __align__(256) float g_KV [(size_t)M_FULL*2*AD];
__device__ __align__(256) float g_Q  [(size_t)M_AG*AD];
__device__ __align__(256) float g_gi [(size_t)M_AG*GID];
__device__ __align__(256) float g_gh [(size_t)M_AG*GID];
__device__ __align__(256) float g_state_t[(size_t)M_FULL*DIN];
__device__ __align__(256) float g_embed_t[(size_t)M_FULL*HD];
__device__ __align__(256) float g_preh_t [(size_t)M_AG*HD];
__device__ __align__(256) float g_att_t  [(size_t)M_AG*AD];
__device__ __align__(256) float g_rew_t  [(size_t)BSZ*RLD];
__device__ __align__(256) float g_h_t    [(size_t)M_AG*HD];
__device__ __align__(256) float g_WstT [HD*DIN];
__device__ __align__(256) float g_WqT  [AD*HD];
__device__ __align__(256) float g_WkvT [2*AD*HD];
__device__ __align__(256) float g_bkv  [2*AD];
__device__ __align__(256) float g_WihT [GID*832];
__device__ __align__(256) float g_WhhT [GID*HD];
__device__ __align__(256) float g_WoutT[OUTD*HD];
__device__ unsigned char g_obs_u8[(size_t)BSZ*NE*NE];
__device__ unsigned char g_sm_u8 [(size_t)BSZ*NE];
__device__ int g_mask_flags;

// ---------------- baseline-PTX helpers ----------------
__device__ __forceinline__ uint32_t smem_u32(const void* p) {
    uint32_t a;
    asm("{ .reg .u64 t; cvta.to.shared.u64 t, %1; cvt.u32.u64 %0, t; }" : "=r"(a) : "l"(p));
    return a;
}
__device__ __forceinline__ void cp16(uint32_t dst, const void* src) {
    asm volatile("cp.async.cg.shared.global [%0], [%1], 16;" :: "r"(dst), "l"(src));
}
#define CP_COMMIT()  asm volatile("cp.async.commit_group;")
#define CP_WAIT(n)   asm volatile("cp.async.wait_group %0;" :: "n"(n))

__device__ __forceinline__ void ldm_x4(uint32_t* r, uint32_t addr) {
    asm volatile("ldmatrix.sync.aligned.m8n8.x4.shared.b16 {%0,%1,%2,%3}, [%4];"
                 : "=r"(r[0]), "=r"(r[1]), "=r"(r[2]), "=r"(r[3]) : "r"(addr));
}
__device__ __forceinline__ void mma_tf32(float* c, const uint32_t* a,
                                         uint32_t b0, uint32_t b1) {
    asm volatile(
        "mma.sync.aligned.m16n8k8.row.col.f32.tf32.tf32.f32 "
        "{%0,%1,%2,%3},{%4,%5,%6,%7},{%8,%9},{%0,%1,%2,%3};"
        : "+f"(c[0]), "+f"(c[1]), "+f"(c[2]), "+f"(c[3])
        : "r"(a[0]), "r"(a[1]), "r"(a[2]), "r"(a[3]), "r"(b0), "r"(b1));
}
__device__ __forceinline__ float rna_tf32(float v) {
    uint32_t r;
    asm("cvt.rna.tf32.f32 %0, %1;" : "=r"(r) : "f"(v));
    return __uint_as_float(r);
}

// ---------------- fused prep: weight transposes + bias concat + flag reset ----
#define PREP_TOTAL 2589184
__global__ void prep_weights_kernel(
    const float* __restrict__ Wst, const float* __restrict__ Wq,
    const float* __restrict__ Wk,  const float* __restrict__ Wv,
    const float* __restrict__ Wih, const float* __restrict__ Whh,
    const float* __restrict__ Wout,
    const float* __restrict__ bk,  const float* __restrict__ bv)
{
    int i = blockIdx.x * blockDim.x + threadIdx.x;
    if (i == 0) g_mask_flags = 0;
    if (i >= PREP_TOTAL) return;

    const float* src; float* dst; int K, N, j;
    if (i < 65536)        { j = i;           src = Wst;  dst = g_WstT;  K = DIN; N = HD; }
    else if (i < 196608)  { j = i - 65536;   src = Wq;   dst = g_WqT;   K = HD;  N = AD; }
    else if (i < 327680)  { j = i - 196608;  src = Wk;   dst = g_WkvT;  K = HD;  N = AD; }
    else if (i < 458752)  { j = i - 327680;  src = Wv;   dst = g_WkvT + AD*HD; K = HD; N = AD; }
    else if (i < 1736704) { j = i - 458752;  src = Wih;  dst = g_WihT;  K = 832; N = GID; }
    else if (i < 2523136) { j = i - 1736704; src = Whh;  dst = g_WhhT;  K = HD;  N = GID; }
    else if (i < 2588672) { j = i - 2523136; src = Wout; dst = g_WoutT; K = HD;  N = OUTD; }
    else {
        j = i - 2588672;
        g_bkv[j] = (j < AD) ? bk[j] : bv[j - AD];
        return;
    }
    int k = j / N, n = j % N;
    dst[(size_t)n * K + k] = rna_tf32(src[j]);
}

// ---------------- fused activations: round state+preh, rew proj, mask detect --
#define ACT_N4A (M_FULL*DIN/4)
#define ACT_N4B (M_AG*HD/4)
#define SEG_REW  (ACT_N4A + ACT_N4B)
#define REW_N    (BSZ*RLD)
#define SEG_DET  (SEG_REW + REW_N)
#define DET_WORDS (BSZ*NE*NE/4)
#define DET_N    (DET_WORDS/8)
#define ACT_TOTAL (SEG_DET + DET_N)
__global__ void conv_acts_kernel(const float* __restrict__ state,
                                 const float* __restrict__ preh,
                                 const float* __restrict__ prer,
                                 const float* __restrict__ Wr,
                                 const float* __restrict__ br,
                                 const unsigned int* __restrict__ obs_w)
{
    int i = blockIdx.x * blockDim.x + threadIdx.x;
    if (i < ACT_N4A + ACT_N4B) {
        const float4* src; float4* dst; int j;
        if (i < ACT_N4A) { j = i;           src = (const float4*)state; dst = (float4*)g_state_t; }
        else             { j = i - ACT_N4A; src = (const float4*)preh;  dst = (float4*)g_preh_t; }
        float4 v = src[j];
        v.x = rna_tf32(v.x); v.y = rna_tf32(v.y);
        v.z = rna_tf32(v.z); v.w = rna_tf32(v.w);
        dst[j] = v;
    } else if (i < SEG_DET) {
        int idx = i - SEG_REW;
        int b = idx >> 6, j = idx & 63;
        g_rew_t[idx] = rna_tf32(fmaxf(fmaf(prer[b], Wr[j], br[j]), 0.0f));
    } else if (i < ACT_TOTAL) {
        int j = (i - SEG_DET) * 8;
        int local = 0;
        #pragma unroll
        for (int w = 0; w < 8; w++) {
            unsigned int v = obs_w[j + w];
            if (v == 0x3F800000u) local |= 2;
            else if (v > 1u) local |= 1;
        }
        if (local & ~g_mask_flags) atomicOr(&g_mask_flags, local);
    }
}

// ---------------- fused vectorized mask conversion ----------------
#define OBS4 (BSZ*NE*NE/4)
#define SM4  (BSZ*NE/4)
__device__ __forceinline__ void conv4(const void* __restrict__ src,
                                      unsigned char* __restrict__ dst,
                                      int i, int mode)
{
    uchar4 o;
    if (mode == 1) {
        uchar4 v = ((const uchar4*)src)[i];
        o = make_uchar4(v.x != 0, v.y != 0, v.z != 0, v.w != 0);
    } else {
        uint4 v = ((const uint4*)src)[i];
        o = make_uchar4(v.x != 0, v.y != 0, v.z != 0, v.w != 0);
    }
    ((uchar4*)dst)[i] = o;
}
__global__ void convert_masks_kernel(const void* __restrict__ obs_src,
                                     const void* __restrict__ sm_src)
{
    int i = blockIdx.x * blockDim.x + threadIdx.x;
    int f = g_mask_flags;
    int mode = (f & 2) ? 2 : ((f & 1) ? 1 : 0);
    if (i < OBS4)            conv4(obs_src, g_obs_u8, i, mode);
    else if (i < OBS4 + SM4) conv4(sm_src,  g_sm_u8,  i - OBS4, mode);
}

// ---------------- tf32 HMMA GEMM core: BK=64, 2-stage, 1 barrier/chunk -------
enum { MODE_DIR = 0, MODE_G16 = 1, MODE_CAT = 2 };
enum { EPI_F32 = 0, EPI_RELU = 1, EPI_MASK = 2, EPI_RELU_RND = 3, EPI_KV = 4 };

template<int BN> struct GP {
    static const int STAGE_ROWS = 128 + BN;
    static const int STAGE_SZ   = STAGE_ROWS * 256;   // 64 fp32 per row
    static const int SMEM       = 2 * STAGE_SZ;       // BN=256: 192K, BN=128: 128K
    static const int WARPS_M    = (BN == 256) ? 2 : 4;
    static const int MT         = 8 / WARPS_M;
};

template<int MODE>
__device__ __forceinline__ const float* a_src(const float* A, const float* A2, const float* A3,
                                              int m, int K, int k0)
{
    if (MODE == MODE_CAT) {
        if (k0 < 512) return A  + (size_t)((m >> 4) * 64 + (m & 15)) * 512 + k0;
        if (k0 < 768) return A2 + (size_t)m * 256 + (k0 - 512);
        return A3 + (size_t)(m >> 4) * 64 + (k0 - 768);
    } else if (MODE == MODE_G16) {
        return A + (size_t)((m >> 4) * 64 + (m & 15)) * K + k0;
    } else {
        return A + (size_t)m * K + k0;
    }
}

template<int BN, int MODE, int EPI>
__device__ __forceinline__ void gemm_core(
    const float* __restrict__ A, const float* __restrict__ A2,
    const float* __restrict__ A3, const float* __restrict__ B,
    const float* __restrict__ bias, float* __restrict__ C,
    const unsigned char* __restrict__ smask,
    int K, int ldc, int bm, int bn, char* sm)
{
    const uint32_t smb = smem_u32(sm);
    const int tid  = threadIdx.x;
    const int wid  = tid >> 5;
    const int lane = tid & 31;

    const int warp_m = wid % GP<BN>::WARPS_M;
    const int warp_n = wid / GP<BN>::WARPS_M;
    const int MT = GP<BN>::MT;

    float acc[GP<BN>::MT][8][4];
    #pragma unroll
    for (int mt = 0; mt < GP<BN>::MT; mt++)
        #pragma unroll
        for (int nt = 0; nt < 8; nt++)
            #pragma unroll
            for (int r = 0; r < 4; r++) acc[mt][nt][r] = 0.0f;

    const int nch = K / 64;

    // stage loader: STAGE_ROWS rows x 16 16B chunks; swizzle chk ^ (row&7)
    auto load_stage = [&](int s, int k0) {
        const uint32_t stg = smb + s * GP<BN>::STAGE_SZ;
        const int iters = GP<BN>::STAGE_ROWS * 16 / 256;
        #pragma unroll
        for (int it = 0; it < iters; it++) {
            int idx  = tid + it * 256;
            int grow = idx >> 4;
            int c16  = idx & 15;
            uint32_t dst = stg + grow * 256 + (uint32_t)(((c16 ^ (grow & 7)) & 15) * 16);
            const float* src;
            if (grow < 128) src = a_src<MODE>(A, A2, A3, bm + grow, K, k0) + c16 * 4;
            else            src = B + (size_t)(bn + grow - 128) * K + k0 + c16 * 4;
            cp16(dst, src);
        }
    };

    load_stage(0, 0);
    CP_COMMIT();

    const int T = lane >> 3;
    const int tr = lane & 7;

    for (int c = 0; c < nch; c++) {
        CP_WAIT(0);
        __syncthreads();
        // prefetch next chunk into the stage consumed at chunk c-1 (safe:
        // every warp passed the barrier above after finishing chunk c-1)
        if (c + 1 < nch) {
            load_stage((c + 1) & 1, (c + 1) * 64);
            CP_COMMIT();
        }

        const uint32_t stg = smb + (c & 1) * GP<BN>::STAGE_SZ;
        #pragma unroll
        for (int s = 0; s < 8; s++) {          // k8 slices: chunks 2s, 2s+1
            uint32_t a[GP<BN>::MT][4];
            #pragma unroll
            for (int mt = 0; mt < GP<BN>::MT; mt++) {
                uint32_t row = warp_m * (MT * 16) + mt * 16 + (T & 1) * 8 + tr;
                uint32_t chk = 2 * s + (T >> 1);
                ldm_x4(a[mt], stg + row * 256 + (((chk ^ (row & 7)) & 15) * 16));
            }
            #pragma unroll
            for (int nq = 0; nq < 4; nq++) {
                uint32_t nrow = 128 + warp_n * 64 + nq * 16 + (T >> 1) * 8 + tr;
                uint32_t chk = 2 * s + (T & 1);
                uint32_t b[4];
                ldm_x4(b, stg + nrow * 256 + (((chk ^ (nrow & 7)) & 15) * 16));
                #pragma unroll
                for (int mt = 0; mt < GP<BN>::MT; mt++) {
                    mma_tf32(acc[mt][nq * 2 + 0], a[mt], b[0], b[1]);
                    mma_tf32(acc[mt][nq * 2 + 1], a[mt], b[2], b[3]);
                }
            }
        }
    }

    #pragma unroll
    for (int mt = 0; mt < GP<BN>::MT; mt++) {
        #pragma unroll
        for (int nt = 0; nt < 8; nt++) {
            const int row0 = bm + warp_m * (MT * 16) + mt * 16 + (lane >> 2);
            const int col  = bn + warp_n * 64 + nt * 8 + (lane & 3) * 2;
            const float b0 = bias[col], b1 = bias[col + 1];
            #pragma unroll
            for (int h = 0; h < 2; h++) {
                const int row = row0 + h * 8;
                float v0 = acc[mt][nt][h * 2 + 0] + b0;
                float v1 = acc[mt][nt][h * 2 + 1] + b1;
                if (EPI == EPI_RELU || EPI == EPI_RELU_RND) {
                    v0 = fmaxf(v0, 0.0f); v1 = fmaxf(v1, 0.0f);
                }
                if (EPI == EPI_KV && col >= AD) {
                    v0 = fmaxf(v0, 0.0f); v1 = fmaxf(v1, 0.0f);
                }
                if (EPI == EPI_MASK) {
                    const int b = row >> 4, q = row & 15;
                    const float keep = smask[b * 64 + q] ? 0.0f : 1.0f;
                    v0 *= keep; v1 *= keep;
                }
                if (EPI == EPI_RELU_RND) { v0 = rna_tf32(v0); v1 = rna_tf32(v1); }
                *(float2*)(C + (size_t)row * ldc + col) = make_float2(v0, v1);
            }
        }
    }
}

// ---------------- GEMM kernels ----------------
__global__ void __launch_bounds__(256, 1)
gemm_embed(const float* __restrict__ A, const float* __restrict__ B,
           const float* __restrict__ bias, float* __restrict__ C)
{
    extern __shared__ char sm[];
    gemm_core<256, MODE_DIR, EPI_RELU_RND>(A, nullptr, nullptr, B, bias, C,
        nullptr, DIN, HD, blockIdx.y * 128, blockIdx.x * 256, sm);
}

__global__ void __launch_bounds__(256, 1)
gemm_kvq(const float* __restrict__ emt,
         const float* __restrict__ wkvT, const float* __restrict__ bkv,
         float* __restrict__ KVb,
         const float* __restrict__ wqT, const float* __restrict__ bq,
         float* __restrict__ Qb)
{
    extern __shared__ char sm[];
    if (blockIdx.z == 0) {
        gemm_core<256, MODE_DIR, EPI_KV>(emt, nullptr, nullptr, wkvT, bkv, KVb,
            nullptr, HD, 2*AD, blockIdx.y * 128, blockIdx.x * 256, sm);
    } else {
        if (blockIdx.x >= 1 || blockIdx.y >= (M_AG/128)) return;
        gemm_core<256, MODE_G16, EPI_F32>(emt, nullptr, nullptr, wqT, bq, Qb,
            nullptr, HD, AD, blockIdx.y * 128, blockIdx.x * 256, sm);
    }
}

__global__ void __launch_bounds__(256, 1)
gemm_gigh(const float* __restrict__ emt, const float* __restrict__ att,
          const float* __restrict__ rwt,
          const float* __restrict__ wihT, const float* __restrict__ bih,
          float* __restrict__ gib,
          const float* __restrict__ pht,
          const float* __restrict__ whhT, const float* __restrict__ bhh,
          float* __restrict__ ghb)
{
    extern __shared__ char sm[];
    if (blockIdx.z == 0) {
        gemm_core<256, MODE_CAT, EPI_F32>(emt, att, rwt, wihT, bih, gib,
            nullptr, HD + AD + RLD, GID, blockIdx.y * 128, blockIdx.x * 256, sm);
    } else {
        gemm_core<256, MODE_DIR, EPI_F32>(pht, nullptr, nullptr, whhT, bhh, ghb,
            nullptr, HD, GID, blockIdx.y * 128, blockIdx.x * 256, sm);
    }
}

__global__ void __launch_bounds__(256, 1)
gemm_out(const float* __restrict__ ht, const float* __restrict__ woutT,
         const float* __restrict__ bout, float* __restrict__ params,
         const unsigned char* __restrict__ smask)
{
    extern __shared__ char sm[];
    gemm_core<128, MODE_DIR, EPI_MASK>(ht, nullptr, nullptr, woutT, bout, params,
        smask, HD, OUTD, blockIdx.y * 128, blockIdx.x * 128, sm);
}

// ---------------- attention ----------------
__global__ void __launch_bounds__(128)
attn_kernel(const float* __restrict__ Qg, const float* __restrict__ KVg,
            const unsigned char* __restrict__ obs, float* __restrict__ outT)
{
    const int b = blockIdx.x >> 3;
    const int h = blockIdx.x & 7;
    const int tid = threadIdx.x;

    __shared__ float Qs[16][32];
    __shared__ float Ks[64][33];
    __shared__ float Vs[64][32];
    __shared__ float Ws[16][68];

    {
        int q = tid >> 3;
        int e4 = (tid & 7) * 4;
        *(float4*)&Qs[q][e4] =
            *(const float4*)(Qg + (size_t)(b * 16 + q) * 256 + h * 32 + e4);
    }
    #pragma unroll
    for (int i = 0; i < 4; i++) {
        int idx = tid + i * 128;
        int k = idx >> 3;
        int e4 = (idx & 7) * 4;
        const float* kvrow = KVg + (size_t)(b * 64 + k) * 512 + h * 32 + e4;
        float4 kv = *(const float4*)kvrow;
        Ks[k][e4 + 0] = kv.x; Ks[k][e4 + 1] = kv.y;
        Ks[k][e4 + 2] = kv.z; Ks[k][e4 + 3] = kv.w;
        *(float4*)&Vs[k][e4] = *(const float4*)(kvrow + 256);
    }
    __syncthreads();

    const float scale = 0.17677669529663687f;
    #pragma unroll
    for (int i = 0; i < 8; i++) {
        int s = tid + i * 128;
        int q = s >> 6;
        int k = s & 63;
        bool masked = (k == q) || (obs[(size_t)b * 4096 + q * 64 + k] != 0);
        float d;
        if (!masked) {
            d = 0.0f;
            #pragma unroll
            for (int e = 0; e < 32; e++) d = fmaf(Qs[q][e], Ks[k][e], d);
            d *= scale;
        } else {
            d = -INFINITY;
        }
        Ws[q][k] = d;
    }
    __syncthreads();

    {
        int q = tid >> 3;
        int l = tid & 7;
        float vals[8];
        float mx = -INFINITY;
        #pragma unroll
        for (int i = 0; i < 8; i++) { vals[i] = Ws[q][l + i * 8]; mx = fmaxf(mx, vals[i]); }
        #pragma unroll
        for (int d2 = 4; d2 > 0; d2 >>= 1) mx = fmaxf(mx, __shfl_xor_sync(0xffffffffu, mx, d2, 8));
        if (mx == -INFINITY) {
            #pragma unroll
            for (int i = 0; i < 8; i++) vals[i] = 0.0f;
        } else {
            float sum = 0.0f;
            #pragma unroll
            for (int i = 0; i < 8; i++) { vals[i] = __expf(vals[i] - mx); sum += vals[i]; }
            #pragma unroll
            for (int d2 = 4; d2 > 0; d2 >>= 1) sum += __shfl_xor_sync(0xffffffffu, sum, d2, 8);
            float inv = 1.0f / sum;
            #pragma unroll
            for (int i = 0; i < 8; i++) vals[i] *= inv;
        }
        #pragma unroll
        for (int i = 0; i < 8; i++) Ws[q][l + i * 8] = vals[i];
    }
    __syncthreads();

    #pragma unroll
    for (int i = 0; i < 4; i++) {
        int o = tid + i * 128;
        int q = o >> 5;
        int e = o & 31;
        float acc = 0.0f;
        #pragma unroll
        for (int k = 0; k < 64; k++) acc = fmaf(Ws[q][k], Vs[k][e], acc);
        outT[(size_t)(b * 16 + q) * 256 + h * 32 + e] = rna_tf32(acc);
    }
}

// ---------------- GRU pointwise ----------------
__device__ __forceinline__ float sigmoidf_(float x) { return 1.0f / (1.0f + __expf(-x)); }

__global__ void gru_kernel(const float* __restrict__ gi, const float* __restrict__ gh,
                           const float* __restrict__ preh,
                           const unsigned char* __restrict__ smask,
                           float* __restrict__ hOut, float* __restrict__ hT)
{
    int t = blockIdx.x * blockDim.x + threadIdx.x;
    if (t >= M_AG * (HD / 4)) return;
    int m  = t >> 7;
    int j4 = (t & 127) * 4;
    size_t gb = (size_t)m * GID + j4;
    size_t hb = (size_t)m * HD + j4;

    float4 ir = *(const float4*)(gi + gb);
    float4 iz = *(const float4*)(gi + gb + 512);
    float4 in = *(const float4*)(gi + gb + 1024);
    float4 hr = *(const float4*)(gh + gb);
    float4 hz = *(const float4*)(gh + gb + 512);
    float4 hn = *(const float4*)(gh + gb + 1024);
    float4 hp = *(const float4*)(preh + hb);

    int b = m >> 4, q = m & 15;
    float keep = smask[b * 64 + q] ? 0.0f : 1.0f;

    float o[4];
    {
        float r = sigmoidf_(ir.x + hr.x), z = sigmoidf_(iz.x + hz.x);
        float n = tanhf(in.x + r * hn.x);
        o[0] = keep * ((1.0f - z) * n + z * hp.x);
    }
    {
        float r = sigmoidf_(ir.y + hr.y), z = sigmoidf_(iz.y + hz.y);
        float n = tanhf(in.y + r * hn.y);
        o[1] = keep * ((1.0f - z) * n + z * hp.y);
    }
    {
        float r = sigmoidf_(ir.z + hr.z), z = sigmoidf_(iz.z + hz.z);
        float n = tanhf(in.z + r * hn.z);
        o[2] = keep * ((1.0f - z) * n + z * hp.z);
    }
    {
        float r = sigmoidf_(ir.w + hr.w), z = sigmoidf_(iz.w + hz.w);
        float n = tanhf(in.w + r * hn.w);
        o[3] = keep * ((1.0f - z) * n + z * hp.w);
    }
    *(float4*)(hOut + hb) = make_float4(o[0], o[1], o[2], o[3]);
    *(float4*)(hT + hb) = make_float4(rna_tf32(o[0]), rna_tf32(o[1]),
                                      rna_tf32(o[2]), rna_tf32(o[3]));
}

// ---------------- launch ----------------
extern "C" void kernel_launch(void* const* d_in, const int* in_sizes, int n_in,
                              void* d_out, int out_size)
{
    (void)in_sizes; (void)out_size;

    const float* state          = (const float*)d_in[0];
    const float* prer           = (const float*)d_in[1];
    const void*  obs_raw        = d_in[2];
    const void*  smask_raw      = d_in[3];
    const float* preh           = (const float*)d_in[4];

    const int base = (n_in >= 22) ? 6 : 5;
    const float* Wst  = (const float*)d_in[base + 0];   const float* bst  = (const float*)d_in[base + 1];
    const float* Wr   = (const float*)d_in[base + 2];   const float* br   = (const float*)d_in[base + 3];
    const float* Wq   = (const float*)d_in[base + 4];   const float* bq   = (const float*)d_in[base + 5];
    const float* Wk   = (const float*)d_in[base + 6];   const float* bk   = (const float*)d_in[base + 7];
    const float* Wv   = (const float*)d_in[base + 8];   const float* bv   = (const float*)d_in[base + 9];
    const float* Wih  = (const float*)d_in[base + 10];  const float* bih  = (const float*)d_in[base + 11];
    const float* Whh  = (const float*)d_in[base + 12];  const float* bhh  = (const float*)d_in[base + 13];
    const float* Wout = (const float*)d_in[base + 14];  const float* bout = (const float*)d_in[base + 15];

    float* params = (float*)d_out;
    float* hOut   = params + (size_t)M_AG * OUTD;

    float *KVb, *Qb, *gib, *ghb;
    float *stt, *emt, *pht, *att, *rwt, *ht;
    float *wstT, *wqT, *wkvT, *bkv, *wihT, *whhT, *woutT;
    unsigned char *obs, *smask;
    cudaGetSymbolAddress((void**)&KVb, g_KV);
    cudaGetSymbolAddress((void**)&Qb,  g_Q);
    cudaGetSymbolAddress((void**)&gib, g_gi);
    cudaGetSymbolAddress((void**)&ghb, g_gh);
    cudaGetSymbolAddress((void**)&stt, g_state_t);
    cudaGetSymbolAddress((void**)&emt, g_embed_t);
    cudaGetSymbolAddress((void**)&pht, g_preh_t);
    cudaGetSymbolAddress((void**)&att, g_att_t);
    cudaGetSymbolAddress((void**)&rwt, g_rew_t);
    cudaGetSymbolAddress((void**)&ht,  g_h_t);
    cudaGetSymbolAddress((void**)&wstT,  g_WstT);
    cudaGetSymbolAddress((void**)&wqT,   g_WqT);
    cudaGetSymbolAddress((void**)&wkvT,  g_WkvT);
    cudaGetSymbolAddress((void**)&bkv,   g_bkv);
    cudaGetSymbolAddress((void**)&wihT,  g_WihT);
    cudaGetSymbolAddress((void**)&whhT,  g_WhhT);
    cudaGetSymbolAddress((void**)&woutT, g_WoutT);
    cudaGetSymbolAddress((void**)&obs,   g_obs_u8);
    cudaGetSymbolAddress((void**)&smask, g_sm_u8);

    const int SM256 = GP<256>::SMEM;   // 196608
    const int SM128 = GP<128>::SMEM;   // 131072
    cudaFuncSetAttribute(gemm_embed, cudaFuncAttributeMaxDynamicSharedMemorySize, SM256);
    cudaFuncSetAttribute(gemm_kvq,   cudaFuncAttributeMaxDynamicSharedMemorySize, SM256);
    cudaFuncSetAttribute(gemm_gigh,  cudaFuncAttributeMaxDynamicSharedMemorySize, SM256);
    cudaFuncSetAttribute(gemm_out,   cudaFuncAttributeMaxDynamicSharedMemorySize, SM128);

    dim3 blk(256);

    // 1. fused weight prep (+ mask-flag reset)
    prep_weights_kernel<<<(PREP_TOTAL + 255)/256, blk>>>(
        Wst, Wq, Wk, Wv, Wih, Whh, Wout, bk, bv);

    // 2. fused: activation rounding + rew projection + mask dtype detection
    conv_acts_kernel<<<(ACT_TOTAL + 255)/256, blk>>>(
        state, preh, prer, Wr, br, (const unsigned int*)obs_raw);

    // 3. fused vectorized mask conversion
    convert_masks_kernel<<<(OBS4 + SM4 + 255)/256, blk>>>(obs_raw, smask_raw);

    // 4. embed = relu(state @ W_state + b), tf32-rounded output  [ncu window]
    gemm_embed<<<dim3(HD/256, M_FULL/128), blk, SM256>>>(stt, wstT, bst, emt);

    // 5. merged KV + Q GEMMs                                     [ncu window]
    gemm_kvq<<<dim3(2*AD/256, M_FULL/128, 2), blk, SM256>>>(
        emt, wkvT, bkv, KVb, wqT, bq, Qb);

    // 6. attention (reads packed KV)
    attn_kernel<<<BSZ*NHD, 128>>>(Qb, KVb, obs, att);

    // 7. merged gi + gh GEMMs
    gemm_gigh<<<dim3(GID/256, M_AG/128, 2), blk, SM256>>>(
        emt, att, rwt, wihT, bih, gib, pht, whhT, bhh, ghb);

    // 8. GRU pointwise -> h
    gru_kernel<<<(M_AG*(HD/4) + 255)/256, blk>>>(gib, ghb, preh, smask, hOut, ht);

    // 9. params = h @ W_out + b, masked
    gemm_out<<<dim3(OUTD/128, M_AG/128), blk, SM128>>>(ht, woutT, bout, params, smask);
}